// round 11
// baseline (speedup 1.0000x reference)
#include <cuda_runtime.h>
#include <math.h>

#define NN 16384      // total nodes (B*N)
#define NB 4096       // nodes per batch
#define KNB 16        // kNN K

// ---------------- scratch ----------------
__device__ float g_xp[NN * 8];
__device__ int   g_nbr[NN * KNB];
__device__ float g_h[NN * 256];
__device__ float g_act0[NN * 256];
__device__ float g_act1[NN * 256];
__device__ float g_als[NN * 4];
__device__ float g_ald[NN * 4];

__device__ __forceinline__ float geluf(float v) {
    return 0.5f * v * (1.0f + erff(v * 0.7071067811865476f));
}

// fp32 -> tf32 (RNA rounding), bit pattern returned as float
__device__ __forceinline__ float cvt_tf32(float x) {
    unsigned r;
    asm("cvt.rna.tf32.f32 %0, %1;" : "=r"(r) : "f"(x));
    return __uint_as_float(r);
}

// one m16n8k8 tf32 MMA, D += A*B
__device__ __forceinline__ void mma8(float* d, const unsigned* a, const unsigned* b) {
    asm volatile(
        "mma.sync.aligned.m16n8k8.row.col.f32.tf32.tf32.f32 "
        "{%0,%1,%2,%3}, {%4,%5,%6,%7}, {%8,%9}, {%0,%1,%2,%3};"
        : "+f"(d[0]), "+f"(d[1]), "+f"(d[2]), "+f"(d[3])
        : "r"(a[0]), "r"(a[1]), "r"(a[2]), "r"(a[3]), "r"(b[0]), "r"(b[1]));
}

__device__ __forceinline__ unsigned smem_u32(const void* p) {
    return (unsigned)__cvta_generic_to_shared(p);
}

__device__ __forceinline__ void ldsm_x4(unsigned* r, unsigned addr) {
    asm volatile("ldmatrix.sync.aligned.m8n8.x4.shared.b16 {%0,%1,%2,%3}, [%4];"
        : "=r"(r[0]), "=r"(r[1]), "=r"(r[2]), "=r"(r[3]) : "r"(addr));
}

// ---------------- prep (range version for launch-order steering) ----------------
__global__ void prep_kernel(const float* __restrict__ x, float* __restrict__ xp, int off) {
    int i = off + blockIdx.x * blockDim.x + threadIdx.x;
    float s = 0.f;
    float v[6];
#pragma unroll
    for (int d = 0; d < 6; d++) { v[d] = x[i * 6 + d]; s += v[d] * v[d]; }
#pragma unroll
    for (int d = 0; d < 6; d++) xp[i * 8 + d] = v[d];
    xp[i * 8 + 6] = s;
    xp[i * 8 + 7] = 0.f;
}

// ---------------- kNN: sample-threshold + buffered exact select ----------------
// One warp per query. Phase 0: T = exact 6th-smallest distance of a 256-sample.
// Phase 1: scan all 4096, append survivors (d <= T) to smem buffer (ballot+popc,
// no dependent chains). Overflow -> compact (keep best 16, tighten T). Underflow
// (<16) -> loosen T and rescan. Phase 2: exact top-16 by (d, idx) warp argmin.
__device__ __forceinline__ float knn_select16(float* bd, int* bi, int cnt, int lane,
                                              int* out16) {
    float ld[10]; int li[10];
#pragma unroll
    for (int t = 0; t < 10; t++) {
        int p = lane + t * 32;
        bool v = p < cnt;
        ld[t] = v ? bd[p] : 1e30f;
        li[t] = v ? bi[p] : 0x7fffffff;
    }
    float lastd = 0.f;
#pragma unroll 1
    for (int r = 0; r < 16; r++) {
        float md = ld[0]; int mi = li[0];
#pragma unroll
        for (int t = 1; t < 10; t++)
            if (ld[t] < md || (ld[t] == md && li[t] < mi)) { md = ld[t]; mi = li[t]; }
#pragma unroll
        for (int off = 16; off; off >>= 1) {
            float od = __shfl_xor_sync(0xffffffffu, md, off);
            int   oi = __shfl_xor_sync(0xffffffffu, mi, off);
            if (od < md || (od == md && oi < mi)) { md = od; mi = oi; }
        }
#pragma unroll
        for (int t = 0; t < 10; t++)
            if (ld[t] == md && li[t] == mi) { ld[t] = 1e30f; li[t] = 0x7fffffff; }
        if (lane == 0) {
            if (out16) out16[r] = mi;
            else { bd[r] = md; bi[r] = mi; }
        }
        lastd = md;
    }
    return lastd;
}

__global__ void __launch_bounds__(256) knn_kernel(const float* __restrict__ xp,
                                                  int* __restrict__ nbr) {
    __shared__ float s_bd[8][292];
    __shared__ int   s_bi[8][292];
    int wid = threadIdx.x >> 5;
    int lane = threadIdx.x & 31;
    int q = blockIdx.x * 8 + wid;
    int base = q & ~(NB - 1);

    const float4* xp4 = (const float4*)xp;
    float4 q0 = xp4[(size_t)q * 2];
    float4 q1 = xp4[(size_t)q * 2 + 1];
    float sqq = q1.z;

    // ---- phase 0: T = exact 6th smallest of 256-sample ----
    float best[6];
#pragma unroll
    for (int k = 0; k < 6; k++) best[k] = 1e30f;
#pragma unroll
    for (int s = 0; s < 8; s++) {
        int g = base + lane + s * 512;
        float4 c0 = xp4[(size_t)g * 2];
        float4 c1 = xp4[(size_t)g * 2 + 1];
        float dot = q0.x * c0.x + q0.y * c0.y + q0.z * c0.z + q0.w * c0.w
                  + q1.x * c1.x + q1.y * c1.y;
        float d = sqq + c1.z - 2.0f * dot;
        if (g == q) d = 1e30f;
        float t = d;
#pragma unroll
        for (int k = 0; k < 6; k++) {
            float lo = fminf(best[k], t);
            t = fmaxf(best[k], t);
            best[k] = lo;
        }
    }
    float T = 0.f;
#pragma unroll
    for (int r = 0; r < 6; r++) {
        float c = best[0];
        float m = c;
#pragma unroll
        for (int off = 16; off; off >>= 1)
            m = fminf(m, __shfl_xor_sync(0xffffffffu, m, off));
        if (r == 5) T = m;
        if (c == m) {
#pragma unroll
            for (int k = 0; k < 5; k++) best[k] = best[k + 1];
            best[5] = 1e30f;
        }
    }

    // ---- phase 1: scan + append survivors; compact on overflow ----
    float* bd = s_bd[wid];
    int*   bi = s_bi[wid];
    int cnt;
    while (true) {
        cnt = 0;
        for (int j0 = 0; j0 < NB; j0 += 32) {
            int g = base + j0 + lane;
            float4 c0 = xp4[(size_t)g * 2];
            float4 c1 = xp4[(size_t)g * 2 + 1];
            float dot = q0.x * c0.x + q0.y * c0.y + q0.z * c0.z + q0.w * c0.w
                      + q1.x * c1.x + q1.y * c1.y;
            float d = sqq + c1.z - 2.0f * dot;
            bool pred = (d <= T) && (g != q);
            unsigned mask = __ballot_sync(0xffffffffu, pred);
            if (mask) {
                int nb = __popc(mask & ((1u << lane) - 1));
                if (pred) { bd[cnt + nb] = d; bi[cnt + nb] = g; }
                cnt += __popc(mask);
                if (cnt > 256) {
                    __syncwarp();
                    T = knn_select16(bd, bi, cnt, lane, nullptr);  // keep best 16
                    cnt = 16;
                    __syncwarp();
                }
            }
        }
        if (cnt >= 16) break;
        T = T * 4.0f + 1e-6f;   // rare underflow: loosen and rescan
    }
    __syncwarp();
    knn_select16(bd, bi, cnt, lane, nbr + q * KNB);
}

// ---------------- layer-1 GEMM (K=6) + direct logits ----------------
__global__ void gemm6_kernel(const float* __restrict__ x, const float* __restrict__ W,
                             const float* __restrict__ a_s, const float* __restrict__ a_d,
                             float* __restrict__ h, float* __restrict__ als,
                             float* __restrict__ ald) {
    __shared__ float sW[6 * 256];
    __shared__ float sAs[256], sAd[256];
    int t = threadIdx.x;
    for (int i = t; i < 6 * 256; i += 256) sW[i] = W[i];
    sAs[t] = a_s[t]; sAd[t] = a_d[t];
    __syncthreads();

    int warp = t >> 5, lane = t & 31;
    int node = blockIdx.x * 8 + warp;
    float xr[6];
#pragma unroll
    for (int d = 0; d < 6; d++) xr[d] = x[node * 6 + d];
    int cbase = lane * 8;
    float out[8];
#pragma unroll
    for (int c = 0; c < 8; c++) {
        float s = 0.f;
#pragma unroll
        for (int d = 0; d < 6; d++) s += xr[d] * sW[d * 256 + cbase + c];
        out[c] = s;
    }
    *(float4*)&h[(size_t)node * 256 + cbase] = make_float4(out[0], out[1], out[2], out[3]);
    *(float4*)&h[(size_t)node * 256 + cbase + 4] = make_float4(out[4], out[5], out[6], out[7]);

    float ps = 0.f, pd = 0.f;
#pragma unroll
    for (int c = 0; c < 8; c++) {
        ps += out[c] * sAs[cbase + c];
        pd += out[c] * sAd[cbase + c];
    }
#pragma unroll
    for (int off = 1; off <= 4; off <<= 1) {
        ps += __shfl_xor_sync(0xffffffffu, ps, off);
        pd += __shfl_xor_sync(0xffffffffu, pd, off);
    }
    if ((lane & 7) == 0) {
        int hh = lane >> 3;
        als[node * 4 + hh] = ps;
        ald[node * 4 + hh] = pd;
    }
}

// ---------------- tf32 tensor-core GEMM: 128x128 tile, ldmatrix A frags ---------
__global__ void __launch_bounds__(256) gemm_mma_kernel(
        const float* __restrict__ A, const float* __restrict__ W,
        const float* __restrict__ bias, float* __restrict__ C,
        int K, int N, int actGelu,
        const float* __restrict__ a_s, const float* __restrict__ a_d,
        float* __restrict__ als, float* __restrict__ ald, int H) {
    __shared__ __align__(16) float As[128][36];
    __shared__ __align__(16) float Ws[32][136];
    __shared__ float s_ls[256], s_ld[256];

    int t = threadIdx.x;
    int warp = t >> 5, lane = t & 31;
    int gid = lane >> 2, tig = lane & 3;
    int wm0 = (warp >> 2) * 64;
    int wn0 = (warp & 3) * 32;
    int row0 = blockIdx.x * 128;
    int c0 = blockIdx.y * 128;

    if (als) { s_ls[t] = 0.f; s_ld[t] = 0.f; }

    float acc[4][4][4];
#pragma unroll
    for (int mt = 0; mt < 4; mt++)
#pragma unroll
        for (int nt = 0; nt < 4; nt++)
#pragma unroll
            for (int r = 0; r < 4; r++) acc[mt][nt][r] = 0.f;

    int aR = t >> 3, aKq = (t & 7) * 4;
    int wK = t >> 5, wC = (t & 31) * 4;

    int row_sel = (lane & 7) + ((lane >> 3) & 1) * 8;
    int ksel = (lane >> 4) & 1;
    unsigned aAddrBase = smem_u32(&As[0][0]) + (unsigned)((wm0 + row_sel) * 144 + ksel * 16);

    float4 aPf[4], wPf[4];
#pragma unroll
    for (int i = 0; i < 4; i++)
        aPf[i] = *(const float4*)&A[(size_t)(row0 + aR + i * 32) * K + aKq];
#pragma unroll
    for (int i = 0; i < 4; i++)
        wPf[i] = *(const float4*)&W[(size_t)(wK + i * 8) * N + c0 + wC];

    int nch = K >> 5;
    for (int ch = 0; ch < nch; ch++) {
#pragma unroll
        for (int i = 0; i < 4; i++) {
            As[aR + i * 32][aKq + 0] = cvt_tf32(aPf[i].x);
            As[aR + i * 32][aKq + 1] = cvt_tf32(aPf[i].y);
            As[aR + i * 32][aKq + 2] = cvt_tf32(aPf[i].z);
            As[aR + i * 32][aKq + 3] = cvt_tf32(aPf[i].w);
        }
#pragma unroll
        for (int i = 0; i < 4; i++) {
            Ws[wK + i * 8][wC + 0] = cvt_tf32(wPf[i].x);
            Ws[wK + i * 8][wC + 1] = cvt_tf32(wPf[i].y);
            Ws[wK + i * 8][wC + 2] = cvt_tf32(wPf[i].z);
            Ws[wK + i * 8][wC + 3] = cvt_tf32(wPf[i].w);
        }
        __syncthreads();

        if (ch + 1 < nch) {
            int k0 = (ch + 1) << 5;
#pragma unroll
            for (int i = 0; i < 4; i++)
                aPf[i] = *(const float4*)&A[(size_t)(row0 + aR + i * 32) * K + k0 + aKq];
#pragma unroll
            for (int i = 0; i < 4; i++)
                wPf[i] = *(const float4*)&W[(size_t)(k0 + wK + i * 8) * N + c0 + wC];
        }

#pragma unroll
        for (int kk8 = 0; kk8 < 4; kk8++) {
            int kb = kk8 * 8;
            unsigned ua[4][4], ub[4][2];
#pragma unroll
            for (int mt = 0; mt < 4; mt++)
                ldsm_x4(ua[mt], aAddrBase + (unsigned)(mt * 2304 + kk8 * 32));
#pragma unroll
            for (int nt = 0; nt < 4; nt++) {
                int cn = wn0 + nt * 8 + gid;
                ub[nt][0] = __float_as_uint(Ws[kb + tig][cn]);
                ub[nt][1] = __float_as_uint(Ws[kb + tig + 4][cn]);
            }
#pragma unroll
            for (int mt = 0; mt < 4; mt++)
#pragma unroll
                for (int nt = 0; nt < 4; nt++)
                    mma8(acc[mt][nt], ua[mt], ub[nt]);
        }
        __syncthreads();
    }

    if (als) {
        float asv[4][2], adv[4][2];
#pragma unroll
        for (int nt = 0; nt < 4; nt++) {
            int col = c0 + wn0 + nt * 8 + 2 * tig;
            asv[nt][0] = a_s[col]; asv[nt][1] = a_s[col + 1];
            adv[nt][0] = a_d[col]; adv[nt][1] = a_d[col + 1];
        }
        int lh = (H == 4) ? (wn0 >> 6) : 0;
#pragma unroll
        for (int mt = 0; mt < 4; mt++) {
            float p0s = 0.f, p1s = 0.f, p0d = 0.f, p1d = 0.f;
#pragma unroll
            for (int nt = 0; nt < 4; nt++) {
                p0s += acc[mt][nt][0] * asv[nt][0] + acc[mt][nt][1] * asv[nt][1];
                p1s += acc[mt][nt][2] * asv[nt][0] + acc[mt][nt][3] * asv[nt][1];
                p0d += acc[mt][nt][0] * adv[nt][0] + acc[mt][nt][1] * adv[nt][1];
                p1d += acc[mt][nt][2] * adv[nt][0] + acc[mt][nt][3] * adv[nt][1];
            }
#pragma unroll
            for (int off = 1; off <= 2; off <<= 1) {
                p0s += __shfl_xor_sync(0xffffffffu, p0s, off);
                p1s += __shfl_xor_sync(0xffffffffu, p1s, off);
                p0d += __shfl_xor_sync(0xffffffffu, p0d, off);
                p1d += __shfl_xor_sync(0xffffffffu, p1d, off);
            }
            if (tig == 0) {
                int rl = wm0 + mt * 16 + gid;
                atomicAdd(&s_ls[lh * 128 + rl], p0s);
                atomicAdd(&s_ls[lh * 128 + rl + 8], p1s);
                atomicAdd(&s_ld[lh * 128 + rl], p0d);
                atomicAdd(&s_ld[lh * 128 + rl + 8], p1d);
            }
        }
        __syncthreads();
        if (H == 4) {
            int row = t & 127, hh = (c0 >> 6) + (t >> 7);
            als[(size_t)(row0 + row) * 4 + hh] = s_ls[(t >> 7) * 128 + row];
            ald[(size_t)(row0 + row) * 4 + hh] = s_ld[(t >> 7) * 128 + row];
        } else if (t < 128) {
            als[row0 + t] = s_ls[t];
            ald[row0 + t] = s_ld[t];
        }
    }

    float bb[4][2];
#pragma unroll
    for (int nt = 0; nt < 4; nt++) {
        if (bias) {
            int col = c0 + wn0 + nt * 8 + 2 * tig;
            bb[nt][0] = bias[col]; bb[nt][1] = bias[col + 1];
        } else { bb[nt][0] = 0.f; bb[nt][1] = 0.f; }
    }
#pragma unroll
    for (int mt = 0; mt < 4; mt++) {
#pragma unroll
        for (int rs = 0; rs < 2; rs++) {
            int row = row0 + wm0 + mt * 16 + gid + rs * 8;
            float* dst = &C[(size_t)row * N + c0 + wn0];
#pragma unroll
            for (int nt = 0; nt < 4; nt++) {
                float v0 = acc[mt][nt][2 * rs] + bb[nt][0];
                float v1 = acc[mt][nt][2 * rs + 1] + bb[nt][1];
                if (actGelu) { v0 = geluf(v0); v1 = geluf(v1); }
                *(float2*)&dst[nt * 8 + 2 * tig] = make_float2(v0, v1);
            }
        }
    }
}

// ---------------- 128x64 FFMA GEMM (MLP layer 2, N=64) ----------------
__global__ void gemm_tile_kernel(const float* __restrict__ A, const float* __restrict__ W,
                                 const float* __restrict__ bias, float* __restrict__ C,
                                 int K, int N, int actGelu) {
    __shared__ float As[16][136];
    __shared__ float Ws[16][64];

    int t = threadIdx.x;
    int tx = t & 15;
    int ty = t >> 4;
    int row0 = blockIdx.x * 128;
    int c0 = blockIdx.y * 64;

    float acc[8][4];
#pragma unroll
    for (int r = 0; r < 8; r++)
#pragma unroll
        for (int c = 0; c < 4; c++) acc[r][c] = 0.f;

    float4 aReg[2], wReg;
    int aR[2], aKq[2];
#pragma unroll
    for (int i = 0; i < 2; i++) {
        int lin = t + i * 256;
        aR[i] = lin >> 2;
        aKq[i] = lin & 3;
    }
    int wK = t >> 4, wC = (t & 15) * 4;

#pragma unroll
    for (int i = 0; i < 2; i++)
        aReg[i] = *(const float4*)&A[(size_t)(row0 + aR[i]) * K + aKq[i] * 4];
    wReg = *(const float4*)&W[(size_t)wK * N + c0 + wC];

    int nchunks = K >> 4;
    for (int ch = 0; ch < nchunks; ch++) {
#pragma unroll
        for (int i = 0; i < 2; i++) {
            As[aKq[i] * 4 + 0][aR[i]] = aReg[i].x;
            As[aKq[i] * 4 + 1][aR[i]] = aReg[i].y;
            As[aKq[i] * 4 + 2][aR[i]] = aReg[i].z;
            As[aKq[i] * 4 + 3][aR[i]] = aReg[i].w;
        }
        *(float4*)&Ws[wK][wC] = wReg;
        __syncthreads();

        if (ch + 1 < nchunks) {
            int k0 = (ch + 1) << 4;
#pragma unroll
            for (int i = 0; i < 2; i++)
                aReg[i] = *(const float4*)&A[(size_t)(row0 + aR[i]) * K + k0 + aKq[i] * 4];
            wReg = *(const float4*)&W[(size_t)(k0 + wK) * N + c0 + wC];
        }

#pragma unroll
        for (int k = 0; k < 16; k++) {
            float4 a0 = *(const float4*)&As[k][ty * 8];
            float4 a1 = *(const float4*)&As[k][ty * 8 + 4];
            float4 wv = *(const float4*)&Ws[k][tx * 4];
            acc[0][0] += a0.x * wv.x; acc[0][1] += a0.x * wv.y; acc[0][2] += a0.x * wv.z; acc[0][3] += a0.x * wv.w;
            acc[1][0] += a0.y * wv.x; acc[1][1] += a0.y * wv.y; acc[1][2] += a0.y * wv.z; acc[1][3] += a0.y * wv.w;
            acc[2][0] += a0.z * wv.x; acc[2][1] += a0.z * wv.y; acc[2][2] += a0.z * wv.z; acc[2][3] += a0.z * wv.w;
            acc[3][0] += a0.w * wv.x; acc[3][1] += a0.w * wv.y; acc[3][2] += a0.w * wv.z; acc[3][3] += a0.w * wv.w;
            acc[4][0] += a1.x * wv.x; acc[4][1] += a1.x * wv.y; acc[4][2] += a1.x * wv.z; acc[4][3] += a1.x * wv.w;
            acc[5][0] += a1.y * wv.x; acc[5][1] += a1.y * wv.y; acc[5][2] += a1.y * wv.z; acc[5][3] += a1.y * wv.w;
            acc[6][0] += a1.z * wv.x; acc[6][1] += a1.z * wv.y; acc[6][2] += a1.z * wv.z; acc[6][3] += a1.z * wv.w;
            acc[7][0] += a1.w * wv.x; acc[7][1] += a1.w * wv.y; acc[7][2] += a1.w * wv.z; acc[7][3] += a1.w * wv.w;
        }
        __syncthreads();
    }

    float4 bb = make_float4(0.f, 0.f, 0.f, 0.f);
    if (bias) bb = *(const float4*)&bias[c0 + tx * 4];
#pragma unroll
    for (int r = 0; r < 8; r++) {
        float v0 = acc[r][0] + bb.x, v1 = acc[r][1] + bb.y,
              v2 = acc[r][2] + bb.z, v3 = acc[r][3] + bb.w;
        if (actGelu) { v0 = geluf(v0); v1 = geluf(v1); v2 = geluf(v2); v3 = geluf(v3); }
        *(float4*)&C[(size_t)(row0 + ty * 8 + r) * N + c0 + tx * 4] =
            make_float4(v0, v1, v2, v3);
    }
}

// ---------------- GAT aggregate (H=4, F=256): TWO warps per node ----------------
__global__ void warp_agg4_kernel(const float* __restrict__ h, const int* __restrict__ nbr,
                                 const float* __restrict__ als, const float* __restrict__ ald,
                                 const float* __restrict__ bias, float* __restrict__ out) {
    int warp = threadIdx.x >> 5, lane = threadIdx.x & 31;
    int i = blockIdx.x * 4 + (warp >> 1);
    int half = warp & 1;

    int nbr_j = i;
    if (lane < 16) nbr_j = nbr[i * KNB + lane];

    float2 sv = *(const float2*)&als[nbr_j * 4 + half * 2];
    float2 dv = *(const float2*)&ald[i * 4 + half * 2];
    float e0 = sv.x + dv.x, e1 = sv.y + dv.y;
    e0 = e0 > 0.f ? e0 : 0.2f * e0;
    e1 = e1 > 0.f ? e1 : 0.2f * e1;
    float m0 = lane < 17 ? e0 : -1e30f, m1 = lane < 17 ? e1 : -1e30f;
#pragma unroll
    for (int off = 16; off > 0; off >>= 1) {
        m0 = fmaxf(m0, __shfl_xor_sync(0xffffffffu, m0, off));
        m1 = fmaxf(m1, __shfl_xor_sync(0xffffffffu, m1, off));
    }
    float x0 = lane < 17 ? __expf(e0 - m0) : 0.f;
    float x1 = lane < 17 ? __expf(e1 - m1) : 0.f;
    float d0 = x0, d1 = x1;
#pragma unroll
    for (int off = 16; off > 0; off >>= 1) {
        d0 += __shfl_xor_sync(0xffffffffu, d0, off);
        d1 += __shfl_xor_sync(0xffffffffu, d1, off);
    }
    float al0 = x0 / d0;
    float al1 = x1 / d1;

    float al1_up = __shfl_up_sync(0xffffffffu, al1, 16);
    float alpha_sel = (lane < 16) ? al0 : al1_up;

    int fbase = half * 128 + lane * 4;
    float4 acc = make_float4(0.f, 0.f, 0.f, 0.f);
#pragma unroll
    for (int j = 0; j < 16; j++) {
        int g = __shfl_sync(0xffffffffu, nbr_j, j);
        float a = __shfl_sync(0xffffffffu, alpha_sel, j, 16);
        float4 v = *(const float4*)(h + g * 256 + fbase);
        acc.x += a * v.x; acc.y += a * v.y; acc.z += a * v.z; acc.w += a * v.w;
    }
    {
        float a0s = __shfl_sync(0xffffffffu, al0, 16);
        float a1s = __shfl_sync(0xffffffffu, al1, 16);
        float a = (lane < 16) ? a0s : a1s;
        float4 v = *(const float4*)(h + i * 256 + fbase);
        acc.x += a * v.x; acc.y += a * v.y; acc.z += a * v.z; acc.w += a * v.w;
    }
    float4 bb = *(const float4*)&bias[fbase];
    float4 o = make_float4(geluf(acc.x + bb.x), geluf(acc.y + bb.y),
                           geluf(acc.z + bb.z), geluf(acc.w + bb.w));
    *(float4*)&out[i * 256 + fbase] = o;
}

// ---------------- GAT aggregate (H=1, F=128) + residual: TWO warps per node ------
__global__ void warp_agg1_kernel(const float* __restrict__ h, const int* __restrict__ nbr,
                                 const float* __restrict__ als, const float* __restrict__ ald,
                                 const float* __restrict__ bias, float* __restrict__ out,
                                 const float* __restrict__ x6, const float* __restrict__ resW,
                                 const float* __restrict__ resb) {
    int warp = threadIdx.x >> 5, lane = threadIdx.x & 31;
    int i = blockIdx.x * 4 + (warp >> 1);
    int half = warp & 1;

    int nbr_j = i;
    if (lane < 16) nbr_j = nbr[i * KNB + lane];

    float e = als[nbr_j] + ald[i];
    e = e > 0.f ? e : 0.2f * e;
    float m = lane < 17 ? e : -1e30f;
#pragma unroll
    for (int off = 16; off > 0; off >>= 1)
        m = fmaxf(m, __shfl_xor_sync(0xffffffffu, m, off));
    float xe = lane < 17 ? __expf(e - m) : 0.f;
    float den = xe;
#pragma unroll
    for (int off = 16; off > 0; off >>= 1)
        den += __shfl_xor_sync(0xffffffffu, den, off);
    float alpha = xe / den;

    int fbase = half * 64 + lane * 2;
    float2 acc = make_float2(0.f, 0.f);
#pragma unroll
    for (int j = 0; j < 17; j++) {
        int g = __shfl_sync(0xffffffffu, nbr_j, j);
        float a = __shfl_sync(0xffffffffu, alpha, j);
        float2 v = *(const float2*)(h + g * 128 + fbase);
        acc.x += a * v.x; acc.y += a * v.y;
    }
    float2 bb = *(const float2*)&bias[fbase];
    float2 o = make_float2(geluf(acc.x + bb.x), geluf(acc.y + bb.y));
    float2 r = *(const float2*)&resb[fbase];
#pragma unroll
    for (int d = 0; d < 6; d++) {
        float xv = x6[i * 6 + d];
        float2 w = *(const float2*)&resW[d * 128 + fbase];
        r.x += xv * w.x; r.y += xv * w.y;
    }
    o.x += r.x; o.y += r.y;
    *(float2*)&out[i * 128 + fbase] = o;
}

// ---------------- final ----------------
__global__ void final_kernel(const float* __restrict__ A, const float* __restrict__ W,
                             const float* __restrict__ b, float* __restrict__ out) {
    __shared__ float Ws[64 * 6];
    __shared__ float sb[6];
    int t = threadIdx.x;
    for (int k = t; k < 64 * 6; k += blockDim.x) Ws[k] = W[k];
    if (t < 6) sb[t] = b[t];
    __syncthreads();

    int i = blockIdx.x * blockDim.x + t;
    if (i >= NN) return;
    float acc[6];
#pragma unroll
    for (int o = 0; o < 6; o++) acc[o] = sb[o];
    const float4* Ar = (const float4*)(A + (size_t)i * 64);
#pragma unroll
    for (int k4 = 0; k4 < 16; k4++) {
        float4 v = Ar[k4];
        int k = k4 * 4;
#pragma unroll
        for (int o = 0; o < 6; o++) {
            acc[o] += v.x * Ws[(k + 0) * 6 + o];
            acc[o] += v.y * Ws[(k + 1) * 6 + o];
            acc[o] += v.z * Ws[(k + 2) * 6 + o];
            acc[o] += v.w * Ws[(k + 3) * 6 + o];
        }
    }
#pragma unroll
    for (int o = 0; o < 6; o++) out[(size_t)i * 6 + o] = acc[o];
}

// ---------------- launch ----------------
extern "C" void kernel_launch(void* const* d_in, const int* in_sizes, int n_in,
                              void* d_out, int out_size) {
    const float* x    = (const float*)d_in[0];
    const float* W1   = (const float*)d_in[1];
    const float* as1  = (const float*)d_in[2];
    const float* ad1  = (const float*)d_in[3];
    const float* b1   = (const float*)d_in[4];
    const float* W2   = (const float*)d_in[5];
    const float* as2  = (const float*)d_in[6];
    const float* ad2  = (const float*)d_in[7];
    const float* b2   = (const float*)d_in[8];
    const float* W3   = (const float*)d_in[9];
    const float* as3  = (const float*)d_in[10];
    const float* ad3  = (const float*)d_in[11];
    const float* b3   = (const float*)d_in[12];
    const float* resW = (const float*)d_in[13];
    const float* resb = (const float*)d_in[14];
    const float* m1W  = (const float*)d_in[15];
    const float* m1b  = (const float*)d_in[16];
    const float* m2W  = (const float*)d_in[17];
    const float* m2b  = (const float*)d_in[18];
    const float* m3W  = (const float*)d_in[19];
    const float* m3b  = (const float*)d_in[20];

    float *xp, *h, *a0, *a1, *als, *ald;
    int* nbr;
    cudaGetSymbolAddress((void**)&xp,  g_xp);
    cudaGetSymbolAddress((void**)&nbr, g_nbr);
    cudaGetSymbolAddress((void**)&h,   g_h);
    cudaGetSymbolAddress((void**)&a0,  g_act0);
    cudaGetSymbolAddress((void**)&a1,  g_act1);
    cudaGetSymbolAddress((void**)&als, g_als);
    cudaGetSymbolAddress((void**)&ald, g_ald);

    // launch order steered so index 5 (ncu -s 5 -c 1) = NEW knn_kernel
    prep_kernel<<<NN / 1024, 256>>>(x, xp, 0);            // 0
    prep_kernel<<<NN / 1024, 256>>>(x, xp, NN / 4);       // 1
    prep_kernel<<<NN / 1024, 256>>>(x, xp, NN / 2);       // 2
    prep_kernel<<<NN / 1024, 256>>>(x, xp, 3 * NN / 4);   // 3
    gemm6_kernel<<<NN / 8, 256>>>(x, W1, as1, ad1, h, als, ald);   // 4
    knn_kernel<<<NN / 8, 256>>>(xp, nbr);                 // 5 <- profiled

    // GAT layer 1 (6 -> 256, H=4)
    warp_agg4_kernel<<<NN / 4, 256>>>(h, nbr, als, ald, b1, a0);

    // GAT layer 2 (256 -> 256, H=4): tf32 MMA + fused logits
    gemm_mma_kernel<<<dim3(NN / 128, 2), 256>>>(a0, W2, nullptr, h, 256, 256, 0,
                                                as2, ad2, als, ald, 4);
    warp_agg4_kernel<<<NN / 4, 256>>>(h, nbr, als, ald, b2, a1);

    // GAT layer 3 (256 -> 128, H=1) + fused residual
    gemm_mma_kernel<<<dim3(NN / 128, 1), 256>>>(a1, W3, nullptr, h, 256, 128, 0,
                                                as3, ad3, als, ald, 1);
    warp_agg1_kernel<<<NN / 4, 256>>>(h, nbr, als, ald, b3, a0, x, resW, resb);

    // MLP
    gemm_mma_kernel<<<dim3(NN / 128, 1), 256>>>(a0, m1W, m1b, a1, 128, 128, 1,
                                                nullptr, nullptr, nullptr, nullptr, 0);
    gemm_tile_kernel<<<dim3(NN / 128, 1), 256>>>(a1, m2W, m2b, h, 128, 64, 1);
    final_kernel<<<NN / 128, 128>>>(h, m3W, m3b, (float*)d_out);
}

// round 12
// speedup vs baseline: 1.0735x; 1.0735x over previous
#include <cuda_runtime.h>
#include <math.h>

#define NN 16384      // total nodes (B*N)
#define NB 4096       // nodes per batch
#define KNB 16        // kNN K

// ---------------- scratch ----------------
__device__ float g_xp[NN * 8];
__device__ int   g_nbr[NN * KNB];
__device__ float g_h[NN * 256];
__device__ float g_act0[NN * 256];
__device__ float g_act1[NN * 256];
__device__ float g_als[NN * 4];
__device__ float g_ald[NN * 4];

__device__ __forceinline__ float geluf(float v) {
    return 0.5f * v * (1.0f + erff(v * 0.7071067811865476f));
}

__device__ __forceinline__ float cvt_tf32(float x) {
    unsigned r;
    asm("cvt.rna.tf32.f32 %0, %1;" : "=r"(r) : "f"(x));
    return __uint_as_float(r);
}

__device__ __forceinline__ void mma8(float* d, const unsigned* a, const unsigned* b) {
    asm volatile(
        "mma.sync.aligned.m16n8k8.row.col.f32.tf32.tf32.f32 "
        "{%0,%1,%2,%3}, {%4,%5,%6,%7}, {%8,%9}, {%0,%1,%2,%3};"
        : "+f"(d[0]), "+f"(d[1]), "+f"(d[2]), "+f"(d[3])
        : "r"(a[0]), "r"(a[1]), "r"(a[2]), "r"(a[3]), "r"(b[0]), "r"(b[1]));
}

__device__ __forceinline__ unsigned smem_u32(const void* p) {
    return (unsigned)__cvta_generic_to_shared(p);
}

__device__ __forceinline__ void ldsm_x4(unsigned* r, unsigned addr) {
    asm volatile("ldmatrix.sync.aligned.m8n8.x4.shared.b16 {%0,%1,%2,%3}, [%4];"
        : "=r"(r[0]), "=r"(r[1]), "=r"(r[2]), "=r"(r[3]) : "r"(addr));
}

// ---------------- prep ----------------
__global__ void prep_kernel(const float* __restrict__ x, float* __restrict__ xp) {
    int i = blockIdx.x * blockDim.x + threadIdx.x;
    if (i >= NN) return;
    float s = 0.f;
    float v[6];
#pragma unroll
    for (int d = 0; d < 6; d++) { v[d] = x[i * 6 + d]; s += v[d] * v[d]; }
#pragma unroll
    for (int d = 0; d < 6; d++) xp[i * 8 + d] = v[d];
    xp[i * 8 + 6] = s;
    xp[i * 8 + 7] = 0.f;
}

// ---------------- kNN: sample-threshold + buffered exact select (v2) ------------
// __noinline__ shared select: exact (d, idx)-lexicographic top-16 of cnt <= 288
// buffered entries; writes either back to buffer (compaction) or to out16.
__device__ __noinline__ float knn_select16(float* bd, int* bi, int cnt, int lane,
                                           int* out16) {
    float ld[9]; int li[9];
#pragma unroll
    for (int t = 0; t < 9; t++) {
        int p = lane + t * 32;
        bool v = p < cnt;
        ld[t] = v ? bd[p] : 1e30f;
        li[t] = v ? bi[p] : 0x7fffffff;
    }
    float lastd = 0.f;
#pragma unroll 1
    for (int r = 0; r < 16; r++) {
        float md = ld[0]; int mi = li[0];
#pragma unroll
        for (int t = 1; t < 9; t++)
            if (ld[t] < md || (ld[t] == md && li[t] < mi)) { md = ld[t]; mi = li[t]; }
#pragma unroll
        for (int off = 16; off; off >>= 1) {
            float od = __shfl_xor_sync(0xffffffffu, md, off);
            int   oi = __shfl_xor_sync(0xffffffffu, mi, off);
            if (od < md || (od == md && oi < mi)) { md = od; mi = oi; }
        }
#pragma unroll
        for (int t = 0; t < 9; t++)
            if (ld[t] == md && li[t] == mi) { ld[t] = 1e30f; li[t] = 0x7fffffff; }
        if (lane == 0) {
            if (out16) out16[r] = mi;
            else { bd[r] = md; bi[r] = mi; }
        }
        lastd = md;
    }
    return lastd;
}

__global__ void __launch_bounds__(256) knn_kernel(const float* __restrict__ xp,
                                                  int* __restrict__ nbr) {
    __shared__ float s_bd[8][292];
    __shared__ int   s_bi[8][292];
    int wid = threadIdx.x >> 5;
    int lane = threadIdx.x & 31;
    int q = blockIdx.x * 8 + wid;
    int base = q & ~(NB - 1);

    const float4* xp4 = (const float4*)xp;
    float4 q0 = xp4[(size_t)q * 2];
    float4 q1 = xp4[(size_t)q * 2 + 1];
    float sqq = q1.z;

    // ---- phase 0: T = exact 6th smallest of 256-sample ----
    float best[6];
#pragma unroll
    for (int k = 0; k < 6; k++) best[k] = 1e30f;
#pragma unroll
    for (int s = 0; s < 8; s++) {
        int g = base + lane + s * 512;
        float4 c0 = xp4[(size_t)g * 2];
        float4 c1 = xp4[(size_t)g * 2 + 1];
        float dot = q0.x * c0.x + q0.y * c0.y + q0.z * c0.z + q0.w * c0.w
                  + q1.x * c1.x + q1.y * c1.y;
        float d = sqq + c1.z - 2.0f * dot;
        if (g == q) d = 1e30f;
        float t = d;
#pragma unroll
        for (int k = 0; k < 6; k++) {
            float lo = fminf(best[k], t);
            t = fmaxf(best[k], t);
            best[k] = lo;
        }
    }
    float T = 0.f;
#pragma unroll
    for (int r = 0; r < 6; r++) {
        float c = best[0];
        float m = c;
#pragma unroll
        for (int off = 16; off; off >>= 1)
            m = fminf(m, __shfl_xor_sync(0xffffffffu, m, off));
        if (r == 5) T = m;
        if (c == m) {
#pragma unroll
            for (int k = 0; k < 5; k++) best[k] = best[k + 1];
            best[5] = 1e30f;
        }
    }

    // ---- phase 1: scan (2 chunks/iter for MLP), append survivors ----
    float* bd = s_bd[wid];
    int*   bi = s_bi[wid];
    int cnt;
    while (true) {
        cnt = 0;
        for (int j0 = 0; j0 < NB; j0 += 64) {
            int gA = base + j0 + lane;
            int gB = gA + 32;
            float4 a0 = xp4[(size_t)gA * 2];
            float4 a1 = xp4[(size_t)gA * 2 + 1];
            float4 b0 = xp4[(size_t)gB * 2];
            float4 b1 = xp4[(size_t)gB * 2 + 1];
            float dotA = q0.x * a0.x + q0.y * a0.y + q0.z * a0.z + q0.w * a0.w
                       + q1.x * a1.x + q1.y * a1.y;
            float dotB = q0.x * b0.x + q0.y * b0.y + q0.z * b0.z + q0.w * b0.w
                       + q1.x * b1.x + q1.y * b1.y;
            float dA = sqq + a1.z - 2.0f * dotA;
            float dB = sqq + b1.z - 2.0f * dotB;
            bool pA = (dA <= T) && (gA != q);
            bool pB = (dB <= T) && (gB != q);
            unsigned mA = __ballot_sync(0xffffffffu, pA);
            unsigned mB = __ballot_sync(0xffffffffu, pB);
            if (mA) {
                int nb = __popc(mA & ((1u << lane) - 1));
                if (pA) { bd[cnt + nb] = dA; bi[cnt + nb] = gA; }
                cnt += __popc(mA);
            }
            if (mB) {
                int nb = __popc(mB & ((1u << lane) - 1));
                if (pB) { bd[cnt + nb] = dB; bi[cnt + nb] = gB; }
                cnt += __popc(mB);
            }
            if (cnt > 256) {
                __syncwarp();
                T = knn_select16(bd, bi, cnt, lane, (int*)0);  // keep best 16, tighten T
                cnt = 16;
                __syncwarp();
            }
        }
        if (cnt >= 16) break;
        T = T * 4.0f + 1e-6f;   // rare underflow: loosen and rescan
    }
    __syncwarp();
    knn_select16(bd, bi, cnt, lane, nbr + q * KNB);
}

// ---------------- layer-1 GEMM (K=6) + direct logits ----------------
__global__ void gemm6_kernel(const float* __restrict__ x, const float* __restrict__ W,
                             const float* __restrict__ a_s, const float* __restrict__ a_d,
                             float* __restrict__ h, float* __restrict__ als,
                             float* __restrict__ ald) {
    __shared__ float sW[6 * 256];
    __shared__ float sAs[256], sAd[256];
    int t = threadIdx.x;
    for (int i = t; i < 6 * 256; i += 256) sW[i] = W[i];
    sAs[t] = a_s[t]; sAd[t] = a_d[t];
    __syncthreads();

    int warp = t >> 5, lane = t & 31;
    int node = blockIdx.x * 8 + warp;
    float xr[6];
#pragma unroll
    for (int d = 0; d < 6; d++) xr[d] = x[node * 6 + d];
    int cbase = lane * 8;
    float out[8];
#pragma unroll
    for (int c = 0; c < 8; c++) {
        float s = 0.f;
#pragma unroll
        for (int d = 0; d < 6; d++) s += xr[d] * sW[d * 256 + cbase + c];
        out[c] = s;
    }
    *(float4*)&h[(size_t)node * 256 + cbase] = make_float4(out[0], out[1], out[2], out[3]);
    *(float4*)&h[(size_t)node * 256 + cbase + 4] = make_float4(out[4], out[5], out[6], out[7]);

    float ps = 0.f, pd = 0.f;
#pragma unroll
    for (int c = 0; c < 8; c++) {
        ps += out[c] * sAs[cbase + c];
        pd += out[c] * sAd[cbase + c];
    }
#pragma unroll
    for (int off = 1; off <= 4; off <<= 1) {
        ps += __shfl_xor_sync(0xffffffffu, ps, off);
        pd += __shfl_xor_sync(0xffffffffu, pd, off);
    }
    if ((lane & 7) == 0) {
        int hh = lane >> 3;
        als[node * 4 + hh] = ps;
        ald[node * 4 + hh] = pd;
    }
}

// ---------------- tf32 tensor-core GEMM: 128x128 tile, ldmatrix A frags ---------
__global__ void __launch_bounds__(256) gemm_mma_kernel(
        const float* __restrict__ A, const float* __restrict__ W,
        const float* __restrict__ bias, float* __restrict__ C,
        int K, int N, int actGelu,
        const float* __restrict__ a_s, const float* __restrict__ a_d,
        float* __restrict__ als, float* __restrict__ ald, int H) {
    __shared__ __align__(16) float As[128][36];
    __shared__ __align__(16) float Ws[32][136];
    __shared__ float s_ls[256], s_ld[256];

    int t = threadIdx.x;
    int warp = t >> 5, lane = t & 31;
    int gid = lane >> 2, tig = lane & 3;
    int wm0 = (warp >> 2) * 64;
    int wn0 = (warp & 3) * 32;
    int row0 = blockIdx.x * 128;
    int c0 = blockIdx.y * 128;

    if (als) { s_ls[t] = 0.f; s_ld[t] = 0.f; }

    float acc[4][4][4];
#pragma unroll
    for (int mt = 0; mt < 4; mt++)
#pragma unroll
        for (int nt = 0; nt < 4; nt++)
#pragma unroll
            for (int r = 0; r < 4; r++) acc[mt][nt][r] = 0.f;

    int aR = t >> 3, aKq = (t & 7) * 4;
    int wK = t >> 5, wC = (t & 31) * 4;

    int row_sel = (lane & 7) + ((lane >> 3) & 1) * 8;
    int ksel = (lane >> 4) & 1;
    unsigned aAddrBase = smem_u32(&As[0][0]) + (unsigned)((wm0 + row_sel) * 144 + ksel * 16);

    float4 aPf[4], wPf[4];
#pragma unroll
    for (int i = 0; i < 4; i++)
        aPf[i] = *(const float4*)&A[(size_t)(row0 + aR + i * 32) * K + aKq];
#pragma unroll
    for (int i = 0; i < 4; i++)
        wPf[i] = *(const float4*)&W[(size_t)(wK + i * 8) * N + c0 + wC];

    int nch = K >> 5;
    for (int ch = 0; ch < nch; ch++) {
#pragma unroll
        for (int i = 0; i < 4; i++) {
            As[aR + i * 32][aKq + 0] = cvt_tf32(aPf[i].x);
            As[aR + i * 32][aKq + 1] = cvt_tf32(aPf[i].y);
            As[aR + i * 32][aKq + 2] = cvt_tf32(aPf[i].z);
            As[aR + i * 32][aKq + 3] = cvt_tf32(aPf[i].w);
        }
#pragma unroll
        for (int i = 0; i < 4; i++) {
            Ws[wK + i * 8][wC + 0] = cvt_tf32(wPf[i].x);
            Ws[wK + i * 8][wC + 1] = cvt_tf32(wPf[i].y);
            Ws[wK + i * 8][wC + 2] = cvt_tf32(wPf[i].z);
            Ws[wK + i * 8][wC + 3] = cvt_tf32(wPf[i].w);
        }
        __syncthreads();

        if (ch + 1 < nch) {
            int k0 = (ch + 1) << 5;
#pragma unroll
            for (int i = 0; i < 4; i++)
                aPf[i] = *(const float4*)&A[(size_t)(row0 + aR + i * 32) * K + k0 + aKq];
#pragma unroll
            for (int i = 0; i < 4; i++)
                wPf[i] = *(const float4*)&W[(size_t)(k0 + wK + i * 8) * N + c0 + wC];
        }

#pragma unroll
        for (int kk8 = 0; kk8 < 4; kk8++) {
            int kb = kk8 * 8;
            unsigned ua[4][4], ub[4][2];
#pragma unroll
            for (int mt = 0; mt < 4; mt++)
                ldsm_x4(ua[mt], aAddrBase + (unsigned)(mt * 2304 + kk8 * 32));
#pragma unroll
            for (int nt = 0; nt < 4; nt++) {
                int cn = wn0 + nt * 8 + gid;
                ub[nt][0] = __float_as_uint(Ws[kb + tig][cn]);
                ub[nt][1] = __float_as_uint(Ws[kb + tig + 4][cn]);
            }
#pragma unroll
            for (int mt = 0; mt < 4; mt++)
#pragma unroll
                for (int nt = 0; nt < 4; nt++)
                    mma8(acc[mt][nt], ua[mt], ub[nt]);
        }
        __syncthreads();
    }

    if (als) {
        float asv[4][2], adv[4][2];
#pragma unroll
        for (int nt = 0; nt < 4; nt++) {
            int col = c0 + wn0 + nt * 8 + 2 * tig;
            asv[nt][0] = a_s[col]; asv[nt][1] = a_s[col + 1];
            adv[nt][0] = a_d[col]; adv[nt][1] = a_d[col + 1];
        }
        int lh = (H == 4) ? (wn0 >> 6) : 0;
#pragma unroll
        for (int mt = 0; mt < 4; mt++) {
            float p0s = 0.f, p1s = 0.f, p0d = 0.f, p1d = 0.f;
#pragma unroll
            for (int nt = 0; nt < 4; nt++) {
                p0s += acc[mt][nt][0] * asv[nt][0] + acc[mt][nt][1] * asv[nt][1];
                p1s += acc[mt][nt][2] * asv[nt][0] + acc[mt][nt][3] * asv[nt][1];
                p0d += acc[mt][nt][0] * adv[nt][0] + acc[mt][nt][1] * adv[nt][1];
                p1d += acc[mt][nt][2] * adv[nt][0] + acc[mt][nt][3] * adv[nt][1];
            }
#pragma unroll
            for (int off = 1; off <= 2; off <<= 1) {
                p0s += __shfl_xor_sync(0xffffffffu, p0s, off);
                p1s += __shfl_xor_sync(0xffffffffu, p1s, off);
                p0d += __shfl_xor_sync(0xffffffffu, p0d, off);
                p1d += __shfl_xor_sync(0xffffffffu, p1d, off);
            }
            if (tig == 0) {
                int rl = wm0 + mt * 16 + gid;
                atomicAdd(&s_ls[lh * 128 + rl], p0s);
                atomicAdd(&s_ls[lh * 128 + rl + 8], p1s);
                atomicAdd(&s_ld[lh * 128 + rl], p0d);
                atomicAdd(&s_ld[lh * 128 + rl + 8], p1d);
            }
        }
        __syncthreads();
        if (H == 4) {
            int row = t & 127, hh = (c0 >> 6) + (t >> 7);
            als[(size_t)(row0 + row) * 4 + hh] = s_ls[(t >> 7) * 128 + row];
            ald[(size_t)(row0 + row) * 4 + hh] = s_ld[(t >> 7) * 128 + row];
        } else if (t < 128) {
            als[row0 + t] = s_ls[t];
            ald[row0 + t] = s_ld[t];
        }
    }

    float bb[4][2];
#pragma unroll
    for (int nt = 0; nt < 4; nt++) {
        if (bias) {
            int col = c0 + wn0 + nt * 8 + 2 * tig;
            bb[nt][0] = bias[col]; bb[nt][1] = bias[col + 1];
        } else { bb[nt][0] = 0.f; bb[nt][1] = 0.f; }
    }
#pragma unroll
    for (int mt = 0; mt < 4; mt++) {
#pragma unroll
        for (int rs = 0; rs < 2; rs++) {
            int row = row0 + wm0 + mt * 16 + gid + rs * 8;
            float* dst = &C[(size_t)row * N + c0 + wn0];
#pragma unroll
            for (int nt = 0; nt < 4; nt++) {
                float v0 = acc[mt][nt][2 * rs] + bb[nt][0];
                float v1 = acc[mt][nt][2 * rs + 1] + bb[nt][1];
                if (actGelu) { v0 = geluf(v0); v1 = geluf(v1); }
                *(float2*)&dst[nt * 8 + 2 * tig] = make_float2(v0, v1);
            }
        }
    }
}

// ---------------- 128x64 FFMA GEMM (MLP layer 2, N=64) ----------------
__global__ void gemm_tile_kernel(const float* __restrict__ A, const float* __restrict__ W,
                                 const float* __restrict__ bias, float* __restrict__ C,
                                 int K, int N, int actGelu) {
    __shared__ float As[16][136];
    __shared__ float Ws[16][64];

    int t = threadIdx.x;
    int tx = t & 15;
    int ty = t >> 4;
    int row0 = blockIdx.x * 128;
    int c0 = blockIdx.y * 64;

    float acc[8][4];
#pragma unroll
    for (int r = 0; r < 8; r++)
#pragma unroll
        for (int c = 0; c < 4; c++) acc[r][c] = 0.f;

    float4 aReg[2], wReg;
    int aR[2], aKq[2];
#pragma unroll
    for (int i = 0; i < 2; i++) {
        int lin = t + i * 256;
        aR[i] = lin >> 2;
        aKq[i] = lin & 3;
    }
    int wK = t >> 4, wC = (t & 15) * 4;

#pragma unroll
    for (int i = 0; i < 2; i++)
        aReg[i] = *(const float4*)&A[(size_t)(row0 + aR[i]) * K + aKq[i] * 4];
    wReg = *(const float4*)&W[(size_t)wK * N + c0 + wC];

    int nchunks = K >> 4;
    for (int ch = 0; ch < nchunks; ch++) {
#pragma unroll
        for (int i = 0; i < 2; i++) {
            As[aKq[i] * 4 + 0][aR[i]] = aReg[i].x;
            As[aKq[i] * 4 + 1][aR[i]] = aReg[i].y;
            As[aKq[i] * 4 + 2][aR[i]] = aReg[i].z;
            As[aKq[i] * 4 + 3][aR[i]] = aReg[i].w;
        }
        *(float4*)&Ws[wK][wC] = wReg;
        __syncthreads();

        if (ch + 1 < nchunks) {
            int k0 = (ch + 1) << 4;
#pragma unroll
            for (int i = 0; i < 2; i++)
                aReg[i] = *(const float4*)&A[(size_t)(row0 + aR[i]) * K + k0 + aKq[i] * 4];
            wReg = *(const float4*)&W[(size_t)(k0 + wK) * N + c0 + wC];
        }

#pragma unroll
        for (int k = 0; k < 16; k++) {
            float4 a0 = *(const float4*)&As[k][ty * 8];
            float4 a1 = *(const float4*)&As[k][ty * 8 + 4];
            float4 wv = *(const float4*)&Ws[k][tx * 4];
            acc[0][0] += a0.x * wv.x; acc[0][1] += a0.x * wv.y; acc[0][2] += a0.x * wv.z; acc[0][3] += a0.x * wv.w;
            acc[1][0] += a0.y * wv.x; acc[1][1] += a0.y * wv.y; acc[1][2] += a0.y * wv.z; acc[1][3] += a0.y * wv.w;
            acc[2][0] += a0.z * wv.x; acc[2][1] += a0.z * wv.y; acc[2][2] += a0.z * wv.z; acc[2][3] += a0.z * wv.w;
            acc[3][0] += a0.w * wv.x; acc[3][1] += a0.w * wv.y; acc[3][2] += a0.w * wv.z; acc[3][3] += a0.w * wv.w;
            acc[4][0] += a1.x * wv.x; acc[4][1] += a1.x * wv.y; acc[4][2] += a1.x * wv.z; acc[4][3] += a1.x * wv.w;
            acc[5][0] += a1.y * wv.x; acc[5][1] += a1.y * wv.y; acc[5][2] += a1.y * wv.z; acc[5][3] += a1.y * wv.w;
            acc[6][0] += a1.z * wv.x; acc[6][1] += a1.z * wv.y; acc[6][2] += a1.z * wv.z; acc[6][3] += a1.z * wv.w;
            acc[7][0] += a1.w * wv.x; acc[7][1] += a1.w * wv.y; acc[7][2] += a1.w * wv.z; acc[7][3] += a1.w * wv.w;
        }
        __syncthreads();
    }

    float4 bb = make_float4(0.f, 0.f, 0.f, 0.f);
    if (bias) bb = *(const float4*)&bias[c0 + tx * 4];
#pragma unroll
    for (int r = 0; r < 8; r++) {
        float v0 = acc[r][0] + bb.x, v1 = acc[r][1] + bb.y,
              v2 = acc[r][2] + bb.z, v3 = acc[r][3] + bb.w;
        if (actGelu) { v0 = geluf(v0); v1 = geluf(v1); v2 = geluf(v2); v3 = geluf(v3); }
        *(float4*)&C[(size_t)(row0 + ty * 8 + r) * N + c0 + tx * 4] =
            make_float4(v0, v1, v2, v3);
    }
}

// ---------------- GAT aggregate (H=4, F=256): TWO warps per node ----------------
__global__ void warp_agg4_kernel(const float* __restrict__ h, const int* __restrict__ nbr,
                                 const float* __restrict__ als, const float* __restrict__ ald,
                                 const float* __restrict__ bias, float* __restrict__ out) {
    int warp = threadIdx.x >> 5, lane = threadIdx.x & 31;
    int i = blockIdx.x * 4 + (warp >> 1);
    int half = warp & 1;

    int nbr_j = i;
    if (lane < 16) nbr_j = nbr[i * KNB + lane];

    float2 sv = *(const float2*)&als[nbr_j * 4 + half * 2];
    float2 dv = *(const float2*)&ald[i * 4 + half * 2];
    float e0 = sv.x + dv.x, e1 = sv.y + dv.y;
    e0 = e0 > 0.f ? e0 : 0.2f * e0;
    e1 = e1 > 0.f ? e1 : 0.2f * e1;
    float m0 = lane < 17 ? e0 : -1e30f, m1 = lane < 17 ? e1 : -1e30f;
#pragma unroll
    for (int off = 16; off > 0; off >>= 1) {
        m0 = fmaxf(m0, __shfl_xor_sync(0xffffffffu, m0, off));
        m1 = fmaxf(m1, __shfl_xor_sync(0xffffffffu, m1, off));
    }
    float x0 = lane < 17 ? __expf(e0 - m0) : 0.f;
    float x1 = lane < 17 ? __expf(e1 - m1) : 0.f;
    float d0 = x0, d1 = x1;
#pragma unroll
    for (int off = 16; off > 0; off >>= 1) {
        d0 += __shfl_xor_sync(0xffffffffu, d0, off);
        d1 += __shfl_xor_sync(0xffffffffu, d1, off);
    }
    float al0 = x0 / d0;
    float al1 = x1 / d1;

    float al1_up = __shfl_up_sync(0xffffffffu, al1, 16);
    float alpha_sel = (lane < 16) ? al0 : al1_up;

    int fbase = half * 128 + lane * 4;
    float4 acc = make_float4(0.f, 0.f, 0.f, 0.f);
#pragma unroll
    for (int j = 0; j < 16; j++) {
        int g = __shfl_sync(0xffffffffu, nbr_j, j);
        float a = __shfl_sync(0xffffffffu, alpha_sel, j, 16);
        float4 v = *(const float4*)(h + g * 256 + fbase);
        acc.x += a * v.x; acc.y += a * v.y; acc.z += a * v.z; acc.w += a * v.w;
    }
    {
        float a0s = __shfl_sync(0xffffffffu, al0, 16);
        float a1s = __shfl_sync(0xffffffffu, al1, 16);
        float a = (lane < 16) ? a0s : a1s;
        float4 v = *(const float4*)(h + i * 256 + fbase);
        acc.x += a * v.x; acc.y += a * v.y; acc.z += a * v.z; acc.w += a * v.w;
    }
    float4 bb = *(const float4*)&bias[fbase];
    float4 o = make_float4(geluf(acc.x + bb.x), geluf(acc.y + bb.y),
                           geluf(acc.z + bb.z), geluf(acc.w + bb.w));
    *(float4*)&out[i * 256 + fbase] = o;
}

// ---------------- GAT aggregate (H=1, F=128) + residual: TWO warps per node ------
__global__ void warp_agg1_kernel(const float* __restrict__ h, const int* __restrict__ nbr,
                                 const float* __restrict__ als, const float* __restrict__ ald,
                                 const float* __restrict__ bias, float* __restrict__ out,
                                 const float* __restrict__ x6, const float* __restrict__ resW,
                                 const float* __restrict__ resb) {
    int warp = threadIdx.x >> 5, lane = threadIdx.x & 31;
    int i = blockIdx.x * 4 + (warp >> 1);
    int half = warp & 1;

    int nbr_j = i;
    if (lane < 16) nbr_j = nbr[i * KNB + lane];

    float e = als[nbr_j] + ald[i];
    e = e > 0.f ? e : 0.2f * e;
    float m = lane < 17 ? e : -1e30f;
#pragma unroll
    for (int off = 16; off > 0; off >>= 1)
        m = fmaxf(m, __shfl_xor_sync(0xffffffffu, m, off));
    float xe = lane < 17 ? __expf(e - m) : 0.f;
    float den = xe;
#pragma unroll
    for (int off = 16; off > 0; off >>= 1)
        den += __shfl_xor_sync(0xffffffffu, den, off);
    float alpha = xe / den;

    int fbase = half * 64 + lane * 2;
    float2 acc = make_float2(0.f, 0.f);
#pragma unroll
    for (int j = 0; j < 17; j++) {
        int g = __shfl_sync(0xffffffffu, nbr_j, j);
        float a = __shfl_sync(0xffffffffu, alpha, j);
        float2 v = *(const float2*)(h + g * 128 + fbase);
        acc.x += a * v.x; acc.y += a * v.y;
    }
    float2 bb = *(const float2*)&bias[fbase];
    float2 o = make_float2(geluf(acc.x + bb.x), geluf(acc.y + bb.y));
    float2 r = *(const float2*)&resb[fbase];
#pragma unroll
    for (int d = 0; d < 6; d++) {
        float xv = x6[i * 6 + d];
        float2 w = *(const float2*)&resW[d * 128 + fbase];
        r.x += xv * w.x; r.y += xv * w.y;
    }
    o.x += r.x; o.y += r.y;
    *(float2*)&out[i * 128 + fbase] = o;
}

// ---------------- final ----------------
__global__ void final_kernel(const float* __restrict__ A, const float* __restrict__ W,
                             const float* __restrict__ b, float* __restrict__ out) {
    __shared__ float Ws[64 * 6];
    __shared__ float sb[6];
    int t = threadIdx.x;
    for (int k = t; k < 64 * 6; k += blockDim.x) Ws[k] = W[k];
    if (t < 6) sb[t] = b[t];
    __syncthreads();

    int i = blockIdx.x * blockDim.x + t;
    if (i >= NN) return;
    float acc[6];
#pragma unroll
    for (int o = 0; o < 6; o++) acc[o] = sb[o];
    const float4* Ar = (const float4*)(A + (size_t)i * 64);
#pragma unroll
    for (int k4 = 0; k4 < 16; k4++) {
        float4 v = Ar[k4];
        int k = k4 * 4;
#pragma unroll
        for (int o = 0; o < 6; o++) {
            acc[o] += v.x * Ws[(k + 0) * 6 + o];
            acc[o] += v.y * Ws[(k + 1) * 6 + o];
            acc[o] += v.z * Ws[(k + 2) * 6 + o];
            acc[o] += v.w * Ws[(k + 3) * 6 + o];
        }
    }
#pragma unroll
    for (int o = 0; o < 6; o++) out[(size_t)i * 6 + o] = acc[o];
}

// ---------------- launch ----------------
extern "C" void kernel_launch(void* const* d_in, const int* in_sizes, int n_in,
                              void* d_out, int out_size) {
    const float* x    = (const float*)d_in[0];
    const float* W1   = (const float*)d_in[1];
    const float* as1  = (const float*)d_in[2];
    const float* ad1  = (const float*)d_in[3];
    const float* b1   = (const float*)d_in[4];
    const float* W2   = (const float*)d_in[5];
    const float* as2  = (const float*)d_in[6];
    const float* ad2  = (const float*)d_in[7];
    const float* b2   = (const float*)d_in[8];
    const float* W3   = (const float*)d_in[9];
    const float* as3  = (const float*)d_in[10];
    const float* ad3  = (const float*)d_in[11];
    const float* b3   = (const float*)d_in[12];
    const float* resW = (const float*)d_in[13];
    const float* resb = (const float*)d_in[14];
    const float* m1W  = (const float*)d_in[15];
    const float* m1b  = (const float*)d_in[16];
    const float* m2W  = (const float*)d_in[17];
    const float* m2b  = (const float*)d_in[18];
    const float* m3W  = (const float*)d_in[19];
    const float* m3b  = (const float*)d_in[20];

    float *xp, *h, *a0, *a1, *als, *ald;
    int* nbr;
    cudaGetSymbolAddress((void**)&xp,  g_xp);
    cudaGetSymbolAddress((void**)&nbr, g_nbr);
    cudaGetSymbolAddress((void**)&h,   g_h);
    cudaGetSymbolAddress((void**)&a0,  g_act0);
    cudaGetSymbolAddress((void**)&a1,  g_act1);
    cudaGetSymbolAddress((void**)&als, g_als);
    cudaGetSymbolAddress((void**)&ald, g_ald);

    prep_kernel<<<NN / 256, 256>>>(x, xp);
    knn_kernel<<<NN / 8, 256>>>(xp, nbr);

    // GAT layer 1 (6 -> 256, H=4)
    gemm6_kernel<<<NN / 8, 256>>>(x, W1, as1, ad1, h, als, ald);
    warp_agg4_kernel<<<NN / 4, 256>>>(h, nbr, als, ald, b1, a0);

    // GAT layer 2 (256 -> 256, H=4): tf32 MMA + fused logits
    gemm_mma_kernel<<<dim3(NN / 128, 2), 256>>>(a0, W2, nullptr, h, 256, 256, 0,
                                                as2, ad2, als, ald, 4);
    warp_agg4_kernel<<<NN / 4, 256>>>(h, nbr, als, ald, b2, a1);

    // GAT layer 3 (256 -> 128, H=1) + fused residual
    gemm_mma_kernel<<<dim3(NN / 128, 1), 256>>>(a1, W3, nullptr, h, 256, 128, 0,
                                                as3, ad3, als, ald, 1);
    warp_agg1_kernel<<<NN / 4, 256>>>(h, nbr, als, ald, b3, a0, x, resW, resb);

    // MLP
    gemm_mma_kernel<<<dim3(NN / 128, 1), 256>>>(a0, m1W, m1b, a1, 128, 128, 1,
                                                nullptr, nullptr, nullptr, nullptr, 0);
    gemm_tile_kernel<<<dim3(NN / 128, 1), 256>>>(a1, m2W, m2b, h, 128, 64, 1);
    final_kernel<<<NN / 128, 128>>>(h, m3W, m3b, (float*)d_out);
}

// round 13
// speedup vs baseline: 1.2487x; 1.1632x over previous
#include <cuda_runtime.h>
#include <math.h>

#define NN 16384      // total nodes (B*N)
#define NB 4096       // nodes per batch
#define KNB 16        // kNN K

// ---------------- scratch ----------------
__device__ float g_xp[NN * 8];
__device__ int   g_nbr[NN * KNB];
__device__ float g_h[NN * 256];
__device__ float g_act0[NN * 256];
__device__ float g_act1[NN * 256];
__device__ float g_als[NN * 4];
__device__ float g_ald[NN * 4];

__device__ __forceinline__ float geluf(float v) {
    return 0.5f * v * (1.0f + erff(v * 0.7071067811865476f));
}

__device__ __forceinline__ float cvt_tf32(float x) {
    unsigned r;
    asm("cvt.rna.tf32.f32 %0, %1;" : "=r"(r) : "f"(x));
    return __uint_as_float(r);
}

__device__ __forceinline__ void mma8(float* d, const unsigned* a, const unsigned* b) {
    asm volatile(
        "mma.sync.aligned.m16n8k8.row.col.f32.tf32.tf32.f32 "
        "{%0,%1,%2,%3}, {%4,%5,%6,%7}, {%8,%9}, {%0,%1,%2,%3};"
        : "+f"(d[0]), "+f"(d[1]), "+f"(d[2]), "+f"(d[3])
        : "r"(a[0]), "r"(a[1]), "r"(a[2]), "r"(a[3]), "r"(b[0]), "r"(b[1]));
}

__device__ __forceinline__ unsigned smem_u32(const void* p) {
    return (unsigned)__cvta_generic_to_shared(p);
}

__device__ __forceinline__ void ldsm_x4(unsigned* r, unsigned addr) {
    asm volatile("ldmatrix.sync.aligned.m8n8.x4.shared.b16 {%0,%1,%2,%3}, [%4];"
        : "=r"(r[0]), "=r"(r[1]), "=r"(r[2]), "=r"(r[3]) : "r"(addr));
}

// ---------------- prep ----------------
__global__ void prep_kernel(const float* __restrict__ x, float* __restrict__ xp) {
    int i = blockIdx.x * blockDim.x + threadIdx.x;
    if (i >= NN) return;
    float s = 0.f;
    float v[6];
#pragma unroll
    for (int d = 0; d < 6; d++) { v[d] = x[i * 6 + d]; s += v[d] * v[d]; }
#pragma unroll
    for (int d = 0; d < 6; d++) xp[i * 8 + d] = v[d];
    xp[i * 8 + 6] = s;
    xp[i * 8 + 7] = 0.f;
}

// ---------------- kNN: warp handles TWO queries; 2-chunk batched loads ----------
// Distributed sorted top-16 lists: lanes 0..15 hold q0's list, lanes 16..31 q1's.
// Loads for both 32-candidate chunks issue before the serialized insert
// processing of chunk A, hiding chunk B's memory latency behind A's chain.
__global__ void __launch_bounds__(256) knn_kernel(const float* __restrict__ xp,
                                                  int* __restrict__ nbr) {
    int gwarp = (blockIdx.x * blockDim.x + threadIdx.x) >> 5;
    int lane = threadIdx.x & 31;
    int q0 = gwarp * 2, q1 = q0 + 1;
    int base = q0 & ~(NB - 1);

    const float4* xp4 = (const float4*)xp;
    float4 qa0 = xp4[(size_t)q0 * 2], qa1 = xp4[(size_t)q0 * 2 + 1];
    float4 qb0 = xp4[(size_t)q1 * 2], qb1 = xp4[(size_t)q1 * 2 + 1];
    float sqa = qa1.z, sqb = qb1.z;

    float s_d = 1e30f;
    int   s_i = -1;
    int ll = lane & 15;

    for (int j0 = 0; j0 < NB; j0 += 64) {
        int gA = base + j0 + lane;
        int gB = gA + 32;
        float4 cA0 = xp4[(size_t)gA * 2];
        float4 cA1 = xp4[(size_t)gA * 2 + 1];
        float4 cB0 = xp4[(size_t)gB * 2];
        float4 cB1 = xp4[(size_t)gB * 2 + 1];

        float daA = sqa + cA1.z - 2.0f * (qa0.x * cA0.x + qa0.y * cA0.y + qa0.z * cA0.z
                  + qa0.w * cA0.w + qa1.x * cA1.x + qa1.y * cA1.y);
        float dbA = sqb + cA1.z - 2.0f * (qb0.x * cA0.x + qb0.y * cA0.y + qb0.z * cA0.z
                  + qb0.w * cA0.w + qb1.x * cA1.x + qb1.y * cA1.y);
        float daB = sqa + cB1.z - 2.0f * (qa0.x * cB0.x + qa0.y * cB0.y + qa0.z * cB0.z
                  + qa0.w * cB0.w + qa1.x * cB1.x + qa1.y * cB1.y);
        float dbB = sqb + cB1.z - 2.0f * (qb0.x * cB0.x + qb0.y * cB0.y + qb0.z * cB0.z
                  + qb0.w * cB0.w + qb1.x * cB1.x + qb1.y * cB1.y);
        if (gA == q0) daA = 1e30f;
        if (gA == q1) dbA = 1e30f;
        if (gB == q0) daB = 1e30f;
        if (gB == q1) dbB = 1e30f;

        // ---- chunk A inserts ----
        {
            float ta = __shfl_sync(0xffffffffu, s_d, 15);
            float tb = __shfl_sync(0xffffffffu, s_d, 31);
            unsigned ba = __ballot_sync(0xffffffffu, daA < ta);
            unsigned bb = __ballot_sync(0xffffffffu, dbA < tb);
            unsigned ball = ba | bb;
            while (ball) {
                int src = __ffs(ball) - 1;
                ball &= ball - 1;
                float va = __shfl_sync(0xffffffffu, daA, src);
                float vb = __shfl_sync(0xffffffffu, dbA, src);
                float v = (lane < 16) ? va : vb;
                bool act = (lane < 16) ? ((ba >> src) & 1u) : ((bb >> src) & 1u);
                float up_d = __shfl_up_sync(0xffffffffu, s_d, 1, 16);
                int   up_i = __shfl_up_sync(0xffffffffu, s_i, 1, 16);
                unsigned lt = __ballot_sync(0xffffffffu, s_d < v);
                int pos = (lane < 16) ? __popc(lt & 0xFFFFu) : __popc(lt >> 16);
                if (act && pos < 16) {
                    if (ll == pos)      { s_d = v;    s_i = base + j0 + src; }
                    else if (ll > pos)  { s_d = up_d; s_i = up_i; }
                }
            }
        }
        // ---- chunk B inserts ----
        {
            float ta = __shfl_sync(0xffffffffu, s_d, 15);
            float tb = __shfl_sync(0xffffffffu, s_d, 31);
            unsigned ba = __ballot_sync(0xffffffffu, daB < ta);
            unsigned bb = __ballot_sync(0xffffffffu, dbB < tb);
            unsigned ball = ba | bb;
            while (ball) {
                int src = __ffs(ball) - 1;
                ball &= ball - 1;
                float va = __shfl_sync(0xffffffffu, daB, src);
                float vb = __shfl_sync(0xffffffffu, dbB, src);
                float v = (lane < 16) ? va : vb;
                bool act = (lane < 16) ? ((ba >> src) & 1u) : ((bb >> src) & 1u);
                float up_d = __shfl_up_sync(0xffffffffu, s_d, 1, 16);
                int   up_i = __shfl_up_sync(0xffffffffu, s_i, 1, 16);
                unsigned lt = __ballot_sync(0xffffffffu, s_d < v);
                int pos = (lane < 16) ? __popc(lt & 0xFFFFu) : __popc(lt >> 16);
                if (act && pos < 16) {
                    if (ll == pos)      { s_d = v;    s_i = base + j0 + 32 + src; }
                    else if (ll > pos)  { s_d = up_d; s_i = up_i; }
                }
            }
        }
    }
    if (lane < 16) nbr[q0 * KNB + ll] = s_i;
    else           nbr[q1 * KNB + ll] = s_i;
}

// ---------------- layer-1 GEMM (K=6) + direct logits ----------------
__global__ void gemm6_kernel(const float* __restrict__ x, const float* __restrict__ W,
                             const float* __restrict__ a_s, const float* __restrict__ a_d,
                             float* __restrict__ h, float* __restrict__ als,
                             float* __restrict__ ald) {
    __shared__ float sW[6 * 256];
    __shared__ float sAs[256], sAd[256];
    int t = threadIdx.x;
    for (int i = t; i < 6 * 256; i += 256) sW[i] = W[i];
    sAs[t] = a_s[t]; sAd[t] = a_d[t];
    __syncthreads();

    int warp = t >> 5, lane = t & 31;
    int node = blockIdx.x * 8 + warp;
    float xr[6];
#pragma unroll
    for (int d = 0; d < 6; d++) xr[d] = x[node * 6 + d];
    int cbase = lane * 8;
    float out[8];
#pragma unroll
    for (int c = 0; c < 8; c++) {
        float s = 0.f;
#pragma unroll
        for (int d = 0; d < 6; d++) s += xr[d] * sW[d * 256 + cbase + c];
        out[c] = s;
    }
    *(float4*)&h[(size_t)node * 256 + cbase] = make_float4(out[0], out[1], out[2], out[3]);
    *(float4*)&h[(size_t)node * 256 + cbase + 4] = make_float4(out[4], out[5], out[6], out[7]);

    float ps = 0.f, pd = 0.f;
#pragma unroll
    for (int c = 0; c < 8; c++) {
        ps += out[c] * sAs[cbase + c];
        pd += out[c] * sAd[cbase + c];
    }
#pragma unroll
    for (int off = 1; off <= 4; off <<= 1) {
        ps += __shfl_xor_sync(0xffffffffu, ps, off);
        pd += __shfl_xor_sync(0xffffffffu, pd, off);
    }
    if ((lane & 7) == 0) {
        int hh = lane >> 3;
        als[node * 4 + hh] = ps;
        ald[node * 4 + hh] = pd;
    }
}

// ---------------- tf32 tensor-core GEMM: 128x128 tile, ldmatrix A frags ---------
__global__ void __launch_bounds__(256) gemm_mma_kernel(
        const float* __restrict__ A, const float* __restrict__ W,
        const float* __restrict__ bias, float* __restrict__ C,
        int K, int N, int actGelu,
        const float* __restrict__ a_s, const float* __restrict__ a_d,
        float* __restrict__ als, float* __restrict__ ald, int H) {
    __shared__ __align__(16) float As[128][36];
    __shared__ __align__(16) float Ws[32][136];
    __shared__ float s_ls[256], s_ld[256];

    int t = threadIdx.x;
    int warp = t >> 5, lane = t & 31;
    int gid = lane >> 2, tig = lane & 3;
    int wm0 = (warp >> 2) * 64;
    int wn0 = (warp & 3) * 32;
    int row0 = blockIdx.x * 128;
    int c0 = blockIdx.y * 128;

    if (als) { s_ls[t] = 0.f; s_ld[t] = 0.f; }

    float acc[4][4][4];
#pragma unroll
    for (int mt = 0; mt < 4; mt++)
#pragma unroll
        for (int nt = 0; nt < 4; nt++)
#pragma unroll
            for (int r = 0; r < 4; r++) acc[mt][nt][r] = 0.f;

    int aR = t >> 3, aKq = (t & 7) * 4;
    int wK = t >> 5, wC = (t & 31) * 4;

    int row_sel = (lane & 7) + ((lane >> 3) & 1) * 8;
    int ksel = (lane >> 4) & 1;
    unsigned aAddrBase = smem_u32(&As[0][0]) + (unsigned)((wm0 + row_sel) * 144 + ksel * 16);

    float4 aPf[4], wPf[4];
#pragma unroll
    for (int i = 0; i < 4; i++)
        aPf[i] = *(const float4*)&A[(size_t)(row0 + aR + i * 32) * K + aKq];
#pragma unroll
    for (int i = 0; i < 4; i++)
        wPf[i] = *(const float4*)&W[(size_t)(wK + i * 8) * N + c0 + wC];

    int nch = K >> 5;
    for (int ch = 0; ch < nch; ch++) {
#pragma unroll
        for (int i = 0; i < 4; i++) {
            As[aR + i * 32][aKq + 0] = cvt_tf32(aPf[i].x);
            As[aR + i * 32][aKq + 1] = cvt_tf32(aPf[i].y);
            As[aR + i * 32][aKq + 2] = cvt_tf32(aPf[i].z);
            As[aR + i * 32][aKq + 3] = cvt_tf32(aPf[i].w);
        }
#pragma unroll
        for (int i = 0; i < 4; i++) {
            Ws[wK + i * 8][wC + 0] = cvt_tf32(wPf[i].x);
            Ws[wK + i * 8][wC + 1] = cvt_tf32(wPf[i].y);
            Ws[wK + i * 8][wC + 2] = cvt_tf32(wPf[i].z);
            Ws[wK + i * 8][wC + 3] = cvt_tf32(wPf[i].w);
        }
        __syncthreads();

        if (ch + 1 < nch) {
            int k0 = (ch + 1) << 5;
#pragma unroll
            for (int i = 0; i < 4; i++)
                aPf[i] = *(const float4*)&A[(size_t)(row0 + aR + i * 32) * K + k0 + aKq];
#pragma unroll
            for (int i = 0; i < 4; i++)
                wPf[i] = *(const float4*)&W[(size_t)(k0 + wK + i * 8) * N + c0 + wC];
        }

#pragma unroll
        for (int kk8 = 0; kk8 < 4; kk8++) {
            int kb = kk8 * 8;
            unsigned ua[4][4], ub[4][2];
#pragma unroll
            for (int mt = 0; mt < 4; mt++)
                ldsm_x4(ua[mt], aAddrBase + (unsigned)(mt * 2304 + kk8 * 32));
#pragma unroll
            for (int nt = 0; nt < 4; nt++) {
                int cn = wn0 + nt * 8 + gid;
                ub[nt][0] = __float_as_uint(Ws[kb + tig][cn]);
                ub[nt][1] = __float_as_uint(Ws[kb + tig + 4][cn]);
            }
#pragma unroll
            for (int mt = 0; mt < 4; mt++)
#pragma unroll
                for (int nt = 0; nt < 4; nt++)
                    mma8(acc[mt][nt], ua[mt], ub[nt]);
        }
        __syncthreads();
    }

    if (als) {
        float asv[4][2], adv[4][2];
#pragma unroll
        for (int nt = 0; nt < 4; nt++) {
            int col = c0 + wn0 + nt * 8 + 2 * tig;
            asv[nt][0] = a_s[col]; asv[nt][1] = a_s[col + 1];
            adv[nt][0] = a_d[col]; adv[nt][1] = a_d[col + 1];
        }
        int lh = (H == 4) ? (wn0 >> 6) : 0;
#pragma unroll
        for (int mt = 0; mt < 4; mt++) {
            float p0s = 0.f, p1s = 0.f, p0d = 0.f, p1d = 0.f;
#pragma unroll
            for (int nt = 0; nt < 4; nt++) {
                p0s += acc[mt][nt][0] * asv[nt][0] + acc[mt][nt][1] * asv[nt][1];
                p1s += acc[mt][nt][2] * asv[nt][0] + acc[mt][nt][3] * asv[nt][1];
                p0d += acc[mt][nt][0] * adv[nt][0] + acc[mt][nt][1] * adv[nt][1];
                p1d += acc[mt][nt][2] * adv[nt][0] + acc[mt][nt][3] * adv[nt][1];
            }
#pragma unroll
            for (int off = 1; off <= 2; off <<= 1) {
                p0s += __shfl_xor_sync(0xffffffffu, p0s, off);
                p1s += __shfl_xor_sync(0xffffffffu, p1s, off);
                p0d += __shfl_xor_sync(0xffffffffu, p0d, off);
                p1d += __shfl_xor_sync(0xffffffffu, p1d, off);
            }
            if (tig == 0) {
                int rl = wm0 + mt * 16 + gid;
                atomicAdd(&s_ls[lh * 128 + rl], p0s);
                atomicAdd(&s_ls[lh * 128 + rl + 8], p1s);
                atomicAdd(&s_ld[lh * 128 + rl], p0d);
                atomicAdd(&s_ld[lh * 128 + rl + 8], p1d);
            }
        }
        __syncthreads();
        if (H == 4) {
            int row = t & 127, hh = (c0 >> 6) + (t >> 7);
            als[(size_t)(row0 + row) * 4 + hh] = s_ls[(t >> 7) * 128 + row];
            ald[(size_t)(row0 + row) * 4 + hh] = s_ld[(t >> 7) * 128 + row];
        } else if (t < 128) {
            als[row0 + t] = s_ls[t];
            ald[row0 + t] = s_ld[t];
        }
    }

    float bb[4][2];
#pragma unroll
    for (int nt = 0; nt < 4; nt++) {
        if (bias) {
            int col = c0 + wn0 + nt * 8 + 2 * tig;
            bb[nt][0] = bias[col]; bb[nt][1] = bias[col + 1];
        } else { bb[nt][0] = 0.f; bb[nt][1] = 0.f; }
    }
#pragma unroll
    for (int mt = 0; mt < 4; mt++) {
#pragma unroll
        for (int rs = 0; rs < 2; rs++) {
            int row = row0 + wm0 + mt * 16 + gid + rs * 8;
            float* dst = &C[(size_t)row * N + c0 + wn0];
#pragma unroll
            for (int nt = 0; nt < 4; nt++) {
                float v0 = acc[mt][nt][2 * rs] + bb[nt][0];
                float v1 = acc[mt][nt][2 * rs + 1] + bb[nt][1];
                if (actGelu) { v0 = geluf(v0); v1 = geluf(v1); }
                *(float2*)&dst[nt * 8 + 2 * tig] = make_float2(v0, v1);
            }
        }
    }
}

// ---------------- 128x64 FFMA GEMM (MLP layer 2, N=64) ----------------
__global__ void gemm_tile_kernel(const float* __restrict__ A, const float* __restrict__ W,
                                 const float* __restrict__ bias, float* __restrict__ C,
                                 int K, int N, int actGelu) {
    __shared__ float As[16][136];
    __shared__ float Ws[16][64];

    int t = threadIdx.x;
    int tx = t & 15;
    int ty = t >> 4;
    int row0 = blockIdx.x * 128;
    int c0 = blockIdx.y * 64;

    float acc[8][4];
#pragma unroll
    for (int r = 0; r < 8; r++)
#pragma unroll
        for (int c = 0; c < 4; c++) acc[r][c] = 0.f;

    float4 aReg[2], wReg;
    int aR[2], aKq[2];
#pragma unroll
    for (int i = 0; i < 2; i++) {
        int lin = t + i * 256;
        aR[i] = lin >> 2;
        aKq[i] = lin & 3;
    }
    int wK = t >> 4, wC = (t & 15) * 4;

#pragma unroll
    for (int i = 0; i < 2; i++)
        aReg[i] = *(const float4*)&A[(size_t)(row0 + aR[i]) * K + aKq[i] * 4];
    wReg = *(const float4*)&W[(size_t)wK * N + c0 + wC];

    int nchunks = K >> 4;
    for (int ch = 0; ch < nchunks; ch++) {
#pragma unroll
        for (int i = 0; i < 2; i++) {
            As[aKq[i] * 4 + 0][aR[i]] = aReg[i].x;
            As[aKq[i] * 4 + 1][aR[i]] = aReg[i].y;
            As[aKq[i] * 4 + 2][aR[i]] = aReg[i].z;
            As[aKq[i] * 4 + 3][aR[i]] = aReg[i].w;
        }
        *(float4*)&Ws[wK][wC] = wReg;
        __syncthreads();

        if (ch + 1 < nchunks) {
            int k0 = (ch + 1) << 4;
#pragma unroll
            for (int i = 0; i < 2; i++)
                aReg[i] = *(const float4*)&A[(size_t)(row0 + aR[i]) * K + k0 + aKq[i] * 4];
            wReg = *(const float4*)&W[(size_t)(k0 + wK) * N + c0 + wC];
        }

#pragma unroll
        for (int k = 0; k < 16; k++) {
            float4 a0 = *(const float4*)&As[k][ty * 8];
            float4 a1 = *(const float4*)&As[k][ty * 8 + 4];
            float4 wv = *(const float4*)&Ws[k][tx * 4];
            acc[0][0] += a0.x * wv.x; acc[0][1] += a0.x * wv.y; acc[0][2] += a0.x * wv.z; acc[0][3] += a0.x * wv.w;
            acc[1][0] += a0.y * wv.x; acc[1][1] += a0.y * wv.y; acc[1][2] += a0.y * wv.z; acc[1][3] += a0.y * wv.w;
            acc[2][0] += a0.z * wv.x; acc[2][1] += a0.z * wv.y; acc[2][2] += a0.z * wv.z; acc[2][3] += a0.z * wv.w;
            acc[3][0] += a0.w * wv.x; acc[3][1] += a0.w * wv.y; acc[3][2] += a0.w * wv.z; acc[3][3] += a0.w * wv.w;
            acc[4][0] += a1.x * wv.x; acc[4][1] += a1.x * wv.y; acc[4][2] += a1.x * wv.z; acc[4][3] += a1.x * wv.w;
            acc[5][0] += a1.y * wv.x; acc[5][1] += a1.y * wv.y; acc[5][2] += a1.y * wv.z; acc[5][3] += a1.y * wv.w;
            acc[6][0] += a1.z * wv.x; acc[6][1] += a1.z * wv.y; acc[6][2] += a1.z * wv.z; acc[6][3] += a1.z * wv.w;
            acc[7][0] += a1.w * wv.x; acc[7][1] += a1.w * wv.y; acc[7][2] += a1.w * wv.z; acc[7][3] += a1.w * wv.w;
        }
        __syncthreads();
    }

    float4 bb = make_float4(0.f, 0.f, 0.f, 0.f);
    if (bias) bb = *(const float4*)&bias[c0 + tx * 4];
#pragma unroll
    for (int r = 0; r < 8; r++) {
        float v0 = acc[r][0] + bb.x, v1 = acc[r][1] + bb.y,
              v2 = acc[r][2] + bb.z, v3 = acc[r][3] + bb.w;
        if (actGelu) { v0 = geluf(v0); v1 = geluf(v1); v2 = geluf(v2); v3 = geluf(v3); }
        *(float4*)&C[(size_t)(row0 + ty * 8 + r) * N + c0 + tx * 4] =
            make_float4(v0, v1, v2, v3);
    }
}

// ---------------- GAT aggregate (H=4, F=256): TWO warps per node ----------------
__global__ void warp_agg4_kernel(const float* __restrict__ h, const int* __restrict__ nbr,
                                 const float* __restrict__ als, const float* __restrict__ ald,
                                 const float* __restrict__ bias, float* __restrict__ out) {
    int warp = threadIdx.x >> 5, lane = threadIdx.x & 31;
    int i = blockIdx.x * 4 + (warp >> 1);
    int half = warp & 1;

    int nbr_j = i;
    if (lane < 16) nbr_j = nbr[i * KNB + lane];

    float2 sv = *(const float2*)&als[nbr_j * 4 + half * 2];
    float2 dv = *(const float2*)&ald[i * 4 + half * 2];
    float e0 = sv.x + dv.x, e1 = sv.y + dv.y;
    e0 = e0 > 0.f ? e0 : 0.2f * e0;
    e1 = e1 > 0.f ? e1 : 0.2f * e1;
    float m0 = lane < 17 ? e0 : -1e30f, m1 = lane < 17 ? e1 : -1e30f;
#pragma unroll
    for (int off = 16; off > 0; off >>= 1) {
        m0 = fmaxf(m0, __shfl_xor_sync(0xffffffffu, m0, off));
        m1 = fmaxf(m1, __shfl_xor_sync(0xffffffffu, m1, off));
    }
    float x0 = lane < 17 ? __expf(e0 - m0) : 0.f;
    float x1 = lane < 17 ? __expf(e1 - m1) : 0.f;
    float d0 = x0, d1 = x1;
#pragma unroll
    for (int off = 16; off > 0; off >>= 1) {
        d0 += __shfl_xor_sync(0xffffffffu, d0, off);
        d1 += __shfl_xor_sync(0xffffffffu, d1, off);
    }
    float al0 = x0 / d0;
    float al1 = x1 / d1;

    float al1_up = __shfl_up_sync(0xffffffffu, al1, 16);
    float alpha_sel = (lane < 16) ? al0 : al1_up;

    int fbase = half * 128 + lane * 4;
    float4 acc = make_float4(0.f, 0.f, 0.f, 0.f);
#pragma unroll
    for (int j = 0; j < 16; j++) {
        int g = __shfl_sync(0xffffffffu, nbr_j, j);
        float a = __shfl_sync(0xffffffffu, alpha_sel, j, 16);
        float4 v = *(const float4*)(h + g * 256 + fbase);
        acc.x += a * v.x; acc.y += a * v.y; acc.z += a * v.z; acc.w += a * v.w;
    }
    {
        float a0s = __shfl_sync(0xffffffffu, al0, 16);
        float a1s = __shfl_sync(0xffffffffu, al1, 16);
        float a = (lane < 16) ? a0s : a1s;
        float4 v = *(const float4*)(h + i * 256 + fbase);
        acc.x += a * v.x; acc.y += a * v.y; acc.z += a * v.z; acc.w += a * v.w;
    }
    float4 bb = *(const float4*)&bias[fbase];
    float4 o = make_float4(geluf(acc.x + bb.x), geluf(acc.y + bb.y),
                           geluf(acc.z + bb.z), geluf(acc.w + bb.w));
    *(float4*)&out[i * 256 + fbase] = o;
}

// ---------------- GAT aggregate (H=1, F=128) + residual: TWO warps per node ------
__global__ void warp_agg1_kernel(const float* __restrict__ h, const int* __restrict__ nbr,
                                 const float* __restrict__ als, const float* __restrict__ ald,
                                 const float* __restrict__ bias, float* __restrict__ out,
                                 const float* __restrict__ x6, const float* __restrict__ resW,
                                 const float* __restrict__ resb) {
    int warp = threadIdx.x >> 5, lane = threadIdx.x & 31;
    int i = blockIdx.x * 4 + (warp >> 1);
    int half = warp & 1;

    int nbr_j = i;
    if (lane < 16) nbr_j = nbr[i * KNB + lane];

    float e = als[nbr_j] + ald[i];
    e = e > 0.f ? e : 0.2f * e;
    float m = lane < 17 ? e : -1e30f;
#pragma unroll
    for (int off = 16; off > 0; off >>= 1)
        m = fmaxf(m, __shfl_xor_sync(0xffffffffu, m, off));
    float xe = lane < 17 ? __expf(e - m) : 0.f;
    float den = xe;
#pragma unroll
    for (int off = 16; off > 0; off >>= 1)
        den += __shfl_xor_sync(0xffffffffu, den, off);
    float alpha = xe / den;

    int fbase = half * 64 + lane * 2;
    float2 acc = make_float2(0.f, 0.f);
#pragma unroll
    for (int j = 0; j < 17; j++) {
        int g = __shfl_sync(0xffffffffu, nbr_j, j);
        float a = __shfl_sync(0xffffffffu, alpha, j);
        float2 v = *(const float2*)(h + g * 128 + fbase);
        acc.x += a * v.x; acc.y += a * v.y;
    }
    float2 bb = *(const float2*)&bias[fbase];
    float2 o = make_float2(geluf(acc.x + bb.x), geluf(acc.y + bb.y));
    float2 r = *(const float2*)&resb[fbase];
#pragma unroll
    for (int d = 0; d < 6; d++) {
        float xv = x6[i * 6 + d];
        float2 w = *(const float2*)&resW[d * 128 + fbase];
        r.x += xv * w.x; r.y += xv * w.y;
    }
    o.x += r.x; o.y += r.y;
    *(float2*)&out[i * 128 + fbase] = o;
}

// ---------------- final ----------------
__global__ void final_kernel(const float* __restrict__ A, const float* __restrict__ W,
                             const float* __restrict__ b, float* __restrict__ out) {
    __shared__ float Ws[64 * 6];
    __shared__ float sb[6];
    int t = threadIdx.x;
    for (int k = t; k < 64 * 6; k += blockDim.x) Ws[k] = W[k];
    if (t < 6) sb[t] = b[t];
    __syncthreads();

    int i = blockIdx.x * blockDim.x + t;
    if (i >= NN) return;
    float acc[6];
#pragma unroll
    for (int o = 0; o < 6; o++) acc[o] = sb[o];
    const float4* Ar = (const float4*)(A + (size_t)i * 64);
#pragma unroll
    for (int k4 = 0; k4 < 16; k4++) {
        float4 v = Ar[k4];
        int k = k4 * 4;
#pragma unroll
        for (int o = 0; o < 6; o++) {
            acc[o] += v.x * Ws[(k + 0) * 6 + o];
            acc[o] += v.y * Ws[(k + 1) * 6 + o];
            acc[o] += v.z * Ws[(k + 2) * 6 + o];
            acc[o] += v.w * Ws[(k + 3) * 6 + o];
        }
    }
#pragma unroll
    for (int o = 0; o < 6; o++) out[(size_t)i * 6 + o] = acc[o];
}

// ---------------- launch ----------------
extern "C" void kernel_launch(void* const* d_in, const int* in_sizes, int n_in,
                              void* d_out, int out_size) {
    const float* x    = (const float*)d_in[0];
    const float* W1   = (const float*)d_in[1];
    const float* as1  = (const float*)d_in[2];
    const float* ad1  = (const float*)d_in[3];
    const float* b1   = (const float*)d_in[4];
    const float* W2   = (const float*)d_in[5];
    const float* as2  = (const float*)d_in[6];
    const float* ad2  = (const float*)d_in[7];
    const float* b2   = (const float*)d_in[8];
    const float* W3   = (const float*)d_in[9];
    const float* as3  = (const float*)d_in[10];
    const float* ad3  = (const float*)d_in[11];
    const float* b3   = (const float*)d_in[12];
    const float* resW = (const float*)d_in[13];
    const float* resb = (const float*)d_in[14];
    const float* m1W  = (const float*)d_in[15];
    const float* m1b  = (const float*)d_in[16];
    const float* m2W  = (const float*)d_in[17];
    const float* m2b  = (const float*)d_in[18];
    const float* m3W  = (const float*)d_in[19];
    const float* m3b  = (const float*)d_in[20];

    float *xp, *h, *a0, *a1, *als, *ald;
    int* nbr;
    cudaGetSymbolAddress((void**)&xp,  g_xp);
    cudaGetSymbolAddress((void**)&nbr, g_nbr);
    cudaGetSymbolAddress((void**)&h,   g_h);
    cudaGetSymbolAddress((void**)&a0,  g_act0);
    cudaGetSymbolAddress((void**)&a1,  g_act1);
    cudaGetSymbolAddress((void**)&als, g_als);
    cudaGetSymbolAddress((void**)&ald, g_ald);

    prep_kernel<<<NN / 256, 256>>>(x, xp);
    knn_kernel<<<NN / 16, 256>>>(xp, nbr);      // 2 queries per warp

    // GAT layer 1 (6 -> 256, H=4)
    gemm6_kernel<<<NN / 8, 256>>>(x, W1, as1, ad1, h, als, ald);
    warp_agg4_kernel<<<NN / 4, 256>>>(h, nbr, als, ald, b1, a0);

    // GAT layer 2 (256 -> 256, H=4): tf32 MMA + fused logits
    gemm_mma_kernel<<<dim3(NN / 128, 2), 256>>>(a0, W2, nullptr, h, 256, 256, 0,
                                                as2, ad2, als, ald, 4);
    warp_agg4_kernel<<<NN / 4, 256>>>(h, nbr, als, ald, b2, a1);

    // GAT layer 3 (256 -> 128, H=1) + fused residual
    gemm_mma_kernel<<<dim3(NN / 128, 1), 256>>>(a1, W3, nullptr, h, 256, 128, 0,
                                                as3, ad3, als, ald, 1);
    warp_agg1_kernel<<<NN / 4, 256>>>(h, nbr, als, ald, b3, a0, x, resW, resb);

    // MLP
    gemm_mma_kernel<<<dim3(NN / 128, 1), 256>>>(a0, m1W, m1b, a1, 128, 128, 1,
                                                nullptr, nullptr, nullptr, nullptr, 0);
    gemm_tile_kernel<<<dim3(NN / 128, 1), 256>>>(a1, m2W, m2b, h, 128, 64, 1);
    final_kernel<<<NN / 128, 128>>>(h, m3W, m3b, (float*)d_out);
}

// round 14
// speedup vs baseline: 1.3104x; 1.0494x over previous
#include <cuda_runtime.h>
#include <math.h>

#define NN 16384      // total nodes (B*N)
#define NB 4096       // nodes per batch
#define KNB 16        // kNN K

// ---------------- scratch ----------------
__device__ float g_xp[NN * 8];
__device__ int   g_nbr[NN * KNB];
__device__ float g_h[NN * 256];
__device__ float g_act0[NN * 256];
__device__ float g_act1[NN * 256];
__device__ float g_als[NN * 4];
__device__ float g_ald[NN * 4];

__device__ __forceinline__ float geluf(float v) {
    return 0.5f * v * (1.0f + erff(v * 0.7071067811865476f));
}

__device__ __forceinline__ float cvt_tf32(float x) {
    unsigned r;
    asm("cvt.rna.tf32.f32 %0, %1;" : "=r"(r) : "f"(x));
    return __uint_as_float(r);
}

__device__ __forceinline__ void mma8(float* d, const unsigned* a, const unsigned* b) {
    asm volatile(
        "mma.sync.aligned.m16n8k8.row.col.f32.tf32.tf32.f32 "
        "{%0,%1,%2,%3}, {%4,%5,%6,%7}, {%8,%9}, {%0,%1,%2,%3};"
        : "+f"(d[0]), "+f"(d[1]), "+f"(d[2]), "+f"(d[3])
        : "r"(a[0]), "r"(a[1]), "r"(a[2]), "r"(a[3]), "r"(b[0]), "r"(b[1]));
}

__device__ __forceinline__ unsigned smem_u32(const void* p) {
    return (unsigned)__cvta_generic_to_shared(p);
}

__device__ __forceinline__ void ldsm_x4(unsigned* r, unsigned addr) {
    asm volatile("ldmatrix.sync.aligned.m8n8.x4.shared.b16 {%0,%1,%2,%3}, [%4];"
        : "=r"(r[0]), "=r"(r[1]), "=r"(r[2]), "=r"(r[3]) : "r"(addr));
}

// ---------------- prep ----------------
__global__ void prep_kernel(const float* __restrict__ x, float* __restrict__ xp) {
    int i = blockIdx.x * blockDim.x + threadIdx.x;
    if (i >= NN) return;
    float s = 0.f;
    float v[6];
#pragma unroll
    for (int d = 0; d < 6; d++) { v[d] = x[i * 6 + d]; s += v[d] * v[d]; }
#pragma unroll
    for (int d = 0; d < 6; d++) xp[i * 8 + d] = v[d];
    xp[i * 8 + 6] = s;
    xp[i * 8 + 7] = 0.f;
}

// ---------------- kNN: warp handles TWO queries; 4-chunk batched loads ----------
// Distributed sorted top-16 lists: lanes 0..15 hold q0's list, lanes 16..31 q1's.
// Loads for FOUR 32-candidate chunks (128 candidates) issue before any insert
// processing, hiding memory latency behind the serialized insert chains.
__global__ void __launch_bounds__(256) knn_kernel(const float* __restrict__ xp,
                                                  int* __restrict__ nbr) {
    int gwarp = (blockIdx.x * blockDim.x + threadIdx.x) >> 5;
    int lane = threadIdx.x & 31;
    int q0 = gwarp * 2, q1 = q0 + 1;
    int base = q0 & ~(NB - 1);

    const float4* xp4 = (const float4*)xp;
    float4 qa0 = xp4[(size_t)q0 * 2], qa1 = xp4[(size_t)q0 * 2 + 1];
    float4 qb0 = xp4[(size_t)q1 * 2], qb1 = xp4[(size_t)q1 * 2 + 1];
    float sqa = qa1.z, sqb = qb1.z;

    float s_d = 1e30f;
    int   s_i = -1;
    int ll = lane & 15;

    for (int j0 = 0; j0 < NB; j0 += 128) {
        float da[4], db[4];
#pragma unroll
        for (int c = 0; c < 4; c++) {
            int g = base + j0 + c * 32 + lane;
            float4 c0 = xp4[(size_t)g * 2];
            float4 c1 = xp4[(size_t)g * 2 + 1];
            float dA = sqa + c1.z - 2.0f * (qa0.x * c0.x + qa0.y * c0.y + qa0.z * c0.z
                     + qa0.w * c0.w + qa1.x * c1.x + qa1.y * c1.y);
            float dB = sqb + c1.z - 2.0f * (qb0.x * c0.x + qb0.y * c0.y + qb0.z * c0.z
                     + qb0.w * c0.w + qb1.x * c1.x + qb1.y * c1.y);
            if (g == q0) dA = 1e30f;
            if (g == q1) dB = 1e30f;
            da[c] = dA; db[c] = dB;
        }
#pragma unroll
        for (int c = 0; c < 4; c++) {
            float ta = __shfl_sync(0xffffffffu, s_d, 15);
            float tb = __shfl_sync(0xffffffffu, s_d, 31);
            unsigned ba = __ballot_sync(0xffffffffu, da[c] < ta);
            unsigned bb = __ballot_sync(0xffffffffu, db[c] < tb);
            unsigned ball = ba | bb;
            while (ball) {
                int src = __ffs(ball) - 1;
                ball &= ball - 1;
                float va = __shfl_sync(0xffffffffu, da[c], src);
                float vb = __shfl_sync(0xffffffffu, db[c], src);
                float v = (lane < 16) ? va : vb;
                bool act = (lane < 16) ? ((ba >> src) & 1u) : ((bb >> src) & 1u);
                float up_d = __shfl_up_sync(0xffffffffu, s_d, 1, 16);
                int   up_i = __shfl_up_sync(0xffffffffu, s_i, 1, 16);
                unsigned lt = __ballot_sync(0xffffffffu, s_d < v);
                int pos = (lane < 16) ? __popc(lt & 0xFFFFu) : __popc(lt >> 16);
                if (act && pos < 16) {
                    if (ll == pos)      { s_d = v;    s_i = base + j0 + c * 32 + src; }
                    else if (ll > pos)  { s_d = up_d; s_i = up_i; }
                }
            }
        }
    }
    if (lane < 16) nbr[q0 * KNB + ll] = s_i;
    else           nbr[q1 * KNB + ll] = s_i;
}

// ---------------- layer-1 GEMM (K=6) + direct logits ----------------
__global__ void gemm6_kernel(const float* __restrict__ x, const float* __restrict__ W,
                             const float* __restrict__ a_s, const float* __restrict__ a_d,
                             float* __restrict__ h, float* __restrict__ als,
                             float* __restrict__ ald) {
    __shared__ float sW[6 * 256];
    __shared__ float sAs[256], sAd[256];
    int t = threadIdx.x;
    for (int i = t; i < 6 * 256; i += 256) sW[i] = W[i];
    sAs[t] = a_s[t]; sAd[t] = a_d[t];
    __syncthreads();

    int warp = t >> 5, lane = t & 31;
    int node = blockIdx.x * 8 + warp;
    float xr[6];
#pragma unroll
    for (int d = 0; d < 6; d++) xr[d] = x[node * 6 + d];
    int cbase = lane * 8;
    float out[8];
#pragma unroll
    for (int c = 0; c < 8; c++) {
        float s = 0.f;
#pragma unroll
        for (int d = 0; d < 6; d++) s += xr[d] * sW[d * 256 + cbase + c];
        out[c] = s;
    }
    *(float4*)&h[(size_t)node * 256 + cbase] = make_float4(out[0], out[1], out[2], out[3]);
    *(float4*)&h[(size_t)node * 256 + cbase + 4] = make_float4(out[4], out[5], out[6], out[7]);

    float ps = 0.f, pd = 0.f;
#pragma unroll
    for (int c = 0; c < 8; c++) {
        ps += out[c] * sAs[cbase + c];
        pd += out[c] * sAd[cbase + c];
    }
#pragma unroll
    for (int off = 1; off <= 4; off <<= 1) {
        ps += __shfl_xor_sync(0xffffffffu, ps, off);
        pd += __shfl_xor_sync(0xffffffffu, pd, off);
    }
    if ((lane & 7) == 0) {
        int hh = lane >> 3;
        als[node * 4 + hh] = ps;
        ald[node * 4 + hh] = pd;
    }
}

// ---------------- tf32 tensor-core GEMM: 128x128 tile, ldmatrix A frags ---------
__global__ void __launch_bounds__(256) gemm_mma_kernel(
        const float* __restrict__ A, const float* __restrict__ W,
        const float* __restrict__ bias, float* __restrict__ C,
        int K, int N, int actGelu,
        const float* __restrict__ a_s, const float* __restrict__ a_d,
        float* __restrict__ als, float* __restrict__ ald, int H) {
    __shared__ __align__(16) float As[128][36];
    __shared__ __align__(16) float Ws[32][136];
    __shared__ float s_ls[256], s_ld[256];

    int t = threadIdx.x;
    int warp = t >> 5, lane = t & 31;
    int gid = lane >> 2, tig = lane & 3;
    int wm0 = (warp >> 2) * 64;
    int wn0 = (warp & 3) * 32;
    int row0 = blockIdx.x * 128;
    int c0 = blockIdx.y * 128;

    if (als) { s_ls[t] = 0.f; s_ld[t] = 0.f; }

    float acc[4][4][4];
#pragma unroll
    for (int mt = 0; mt < 4; mt++)
#pragma unroll
        for (int nt = 0; nt < 4; nt++)
#pragma unroll
            for (int r = 0; r < 4; r++) acc[mt][nt][r] = 0.f;

    int aR = t >> 3, aKq = (t & 7) * 4;
    int wK = t >> 5, wC = (t & 31) * 4;

    int row_sel = (lane & 7) + ((lane >> 3) & 1) * 8;
    int ksel = (lane >> 4) & 1;
    unsigned aAddrBase = smem_u32(&As[0][0]) + (unsigned)((wm0 + row_sel) * 144 + ksel * 16);

    float4 aPf[4], wPf[4];
#pragma unroll
    for (int i = 0; i < 4; i++)
        aPf[i] = *(const float4*)&A[(size_t)(row0 + aR + i * 32) * K + aKq];
#pragma unroll
    for (int i = 0; i < 4; i++)
        wPf[i] = *(const float4*)&W[(size_t)(wK + i * 8) * N + c0 + wC];

    int nch = K >> 5;
    for (int ch = 0; ch < nch; ch++) {
#pragma unroll
        for (int i = 0; i < 4; i++) {
            As[aR + i * 32][aKq + 0] = cvt_tf32(aPf[i].x);
            As[aR + i * 32][aKq + 1] = cvt_tf32(aPf[i].y);
            As[aR + i * 32][aKq + 2] = cvt_tf32(aPf[i].z);
            As[aR + i * 32][aKq + 3] = cvt_tf32(aPf[i].w);
        }
#pragma unroll
        for (int i = 0; i < 4; i++) {
            Ws[wK + i * 8][wC + 0] = cvt_tf32(wPf[i].x);
            Ws[wK + i * 8][wC + 1] = cvt_tf32(wPf[i].y);
            Ws[wK + i * 8][wC + 2] = cvt_tf32(wPf[i].z);
            Ws[wK + i * 8][wC + 3] = cvt_tf32(wPf[i].w);
        }
        __syncthreads();

        if (ch + 1 < nch) {
            int k0 = (ch + 1) << 5;
#pragma unroll
            for (int i = 0; i < 4; i++)
                aPf[i] = *(const float4*)&A[(size_t)(row0 + aR + i * 32) * K + k0 + aKq];
#pragma unroll
            for (int i = 0; i < 4; i++)
                wPf[i] = *(const float4*)&W[(size_t)(k0 + wK + i * 8) * N + c0 + wC];
        }

#pragma unroll
        for (int kk8 = 0; kk8 < 4; kk8++) {
            int kb = kk8 * 8;
            unsigned ua[4][4], ub[4][2];
#pragma unroll
            for (int mt = 0; mt < 4; mt++)
                ldsm_x4(ua[mt], aAddrBase + (unsigned)(mt * 2304 + kk8 * 32));
#pragma unroll
            for (int nt = 0; nt < 4; nt++) {
                int cn = wn0 + nt * 8 + gid;
                ub[nt][0] = __float_as_uint(Ws[kb + tig][cn]);
                ub[nt][1] = __float_as_uint(Ws[kb + tig + 4][cn]);
            }
#pragma unroll
            for (int mt = 0; mt < 4; mt++)
#pragma unroll
                for (int nt = 0; nt < 4; nt++)
                    mma8(acc[mt][nt], ua[mt], ub[nt]);
        }
        __syncthreads();
    }

    if (als) {
        float asv[4][2], adv[4][2];
#pragma unroll
        for (int nt = 0; nt < 4; nt++) {
            int col = c0 + wn0 + nt * 8 + 2 * tig;
            asv[nt][0] = a_s[col]; asv[nt][1] = a_s[col + 1];
            adv[nt][0] = a_d[col]; adv[nt][1] = a_d[col + 1];
        }
        int lh = (H == 4) ? (wn0 >> 6) : 0;
#pragma unroll
        for (int mt = 0; mt < 4; mt++) {
            float p0s = 0.f, p1s = 0.f, p0d = 0.f, p1d = 0.f;
#pragma unroll
            for (int nt = 0; nt < 4; nt++) {
                p0s += acc[mt][nt][0] * asv[nt][0] + acc[mt][nt][1] * asv[nt][1];
                p1s += acc[mt][nt][2] * asv[nt][0] + acc[mt][nt][3] * asv[nt][1];
                p0d += acc[mt][nt][0] * adv[nt][0] + acc[mt][nt][1] * adv[nt][1];
                p1d += acc[mt][nt][2] * adv[nt][0] + acc[mt][nt][3] * adv[nt][1];
            }
#pragma unroll
            for (int off = 1; off <= 2; off <<= 1) {
                p0s += __shfl_xor_sync(0xffffffffu, p0s, off);
                p1s += __shfl_xor_sync(0xffffffffu, p1s, off);
                p0d += __shfl_xor_sync(0xffffffffu, p0d, off);
                p1d += __shfl_xor_sync(0xffffffffu, p1d, off);
            }
            if (tig == 0) {
                int rl = wm0 + mt * 16 + gid;
                atomicAdd(&s_ls[lh * 128 + rl], p0s);
                atomicAdd(&s_ls[lh * 128 + rl + 8], p1s);
                atomicAdd(&s_ld[lh * 128 + rl], p0d);
                atomicAdd(&s_ld[lh * 128 + rl + 8], p1d);
            }
        }
        __syncthreads();
        if (H == 4) {
            int row = t & 127, hh = (c0 >> 6) + (t >> 7);
            als[(size_t)(row0 + row) * 4 + hh] = s_ls[(t >> 7) * 128 + row];
            ald[(size_t)(row0 + row) * 4 + hh] = s_ld[(t >> 7) * 128 + row];
        } else if (t < 128) {
            als[row0 + t] = s_ls[t];
            ald[row0 + t] = s_ld[t];
        }
    }

    float bb[4][2];
#pragma unroll
    for (int nt = 0; nt < 4; nt++) {
        if (bias) {
            int col = c0 + wn0 + nt * 8 + 2 * tig;
            bb[nt][0] = bias[col]; bb[nt][1] = bias[col + 1];
        } else { bb[nt][0] = 0.f; bb[nt][1] = 0.f; }
    }
#pragma unroll
    for (int mt = 0; mt < 4; mt++) {
#pragma unroll
        for (int rs = 0; rs < 2; rs++) {
            int row = row0 + wm0 + mt * 16 + gid + rs * 8;
            float* dst = &C[(size_t)row * N + c0 + wn0];
#pragma unroll
            for (int nt = 0; nt < 4; nt++) {
                float v0 = acc[mt][nt][2 * rs] + bb[nt][0];
                float v1 = acc[mt][nt][2 * rs + 1] + bb[nt][1];
                if (actGelu) { v0 = geluf(v0); v1 = geluf(v1); }
                *(float2*)&dst[nt * 8 + 2 * tig] = make_float2(v0, v1);
            }
        }
    }
}

// ---------------- 128x64 FFMA GEMM (MLP layer 2, N=64) ----------------
__global__ void gemm_tile_kernel(const float* __restrict__ A, const float* __restrict__ W,
                                 const float* __restrict__ bias, float* __restrict__ C,
                                 int K, int N, int actGelu) {
    __shared__ float As[16][136];
    __shared__ float Ws[16][64];

    int t = threadIdx.x;
    int tx = t & 15;
    int ty = t >> 4;
    int row0 = blockIdx.x * 128;
    int c0 = blockIdx.y * 64;

    float acc[8][4];
#pragma unroll
    for (int r = 0; r < 8; r++)
#pragma unroll
        for (int c = 0; c < 4; c++) acc[r][c] = 0.f;

    float4 aReg[2], wReg;
    int aR[2], aKq[2];
#pragma unroll
    for (int i = 0; i < 2; i++) {
        int lin = t + i * 256;
        aR[i] = lin >> 2;
        aKq[i] = lin & 3;
    }
    int wK = t >> 4, wC = (t & 15) * 4;

#pragma unroll
    for (int i = 0; i < 2; i++)
        aReg[i] = *(const float4*)&A[(size_t)(row0 + aR[i]) * K + aKq[i] * 4];
    wReg = *(const float4*)&W[(size_t)wK * N + c0 + wC];

    int nchunks = K >> 4;
    for (int ch = 0; ch < nchunks; ch++) {
#pragma unroll
        for (int i = 0; i < 2; i++) {
            As[aKq[i] * 4 + 0][aR[i]] = aReg[i].x;
            As[aKq[i] * 4 + 1][aR[i]] = aReg[i].y;
            As[aKq[i] * 4 + 2][aR[i]] = aReg[i].z;
            As[aKq[i] * 4 + 3][aR[i]] = aReg[i].w;
        }
        *(float4*)&Ws[wK][wC] = wReg;
        __syncthreads();

        if (ch + 1 < nchunks) {
            int k0 = (ch + 1) << 4;
#pragma unroll
            for (int i = 0; i < 2; i++)
                aReg[i] = *(const float4*)&A[(size_t)(row0 + aR[i]) * K + k0 + aKq[i] * 4];
            wReg = *(const float4*)&W[(size_t)(k0 + wK) * N + c0 + wC];
        }

#pragma unroll
        for (int k = 0; k < 16; k++) {
            float4 a0 = *(const float4*)&As[k][ty * 8];
            float4 a1 = *(const float4*)&As[k][ty * 8 + 4];
            float4 wv = *(const float4*)&Ws[k][tx * 4];
            acc[0][0] += a0.x * wv.x; acc[0][1] += a0.x * wv.y; acc[0][2] += a0.x * wv.z; acc[0][3] += a0.x * wv.w;
            acc[1][0] += a0.y * wv.x; acc[1][1] += a0.y * wv.y; acc[1][2] += a0.y * wv.z; acc[1][3] += a0.y * wv.w;
            acc[2][0] += a0.z * wv.x; acc[2][1] += a0.z * wv.y; acc[2][2] += a0.z * wv.z; acc[2][3] += a0.z * wv.w;
            acc[3][0] += a0.w * wv.x; acc[3][1] += a0.w * wv.y; acc[3][2] += a0.w * wv.z; acc[3][3] += a0.w * wv.w;
            acc[4][0] += a1.x * wv.x; acc[4][1] += a1.x * wv.y; acc[4][2] += a1.x * wv.z; acc[4][3] += a1.x * wv.w;
            acc[5][0] += a1.y * wv.x; acc[5][1] += a1.y * wv.y; acc[5][2] += a1.y * wv.z; acc[5][3] += a1.y * wv.w;
            acc[6][0] += a1.z * wv.x; acc[6][1] += a1.z * wv.y; acc[6][2] += a1.z * wv.z; acc[6][3] += a1.z * wv.w;
            acc[7][0] += a1.w * wv.x; acc[7][1] += a1.w * wv.y; acc[7][2] += a1.w * wv.z; acc[7][3] += a1.w * wv.w;
        }
        __syncthreads();
    }

    float4 bb = make_float4(0.f, 0.f, 0.f, 0.f);
    if (bias) bb = *(const float4*)&bias[c0 + tx * 4];
#pragma unroll
    for (int r = 0; r < 8; r++) {
        float v0 = acc[r][0] + bb.x, v1 = acc[r][1] + bb.y,
              v2 = acc[r][2] + bb.z, v3 = acc[r][3] + bb.w;
        if (actGelu) { v0 = geluf(v0); v1 = geluf(v1); v2 = geluf(v2); v3 = geluf(v3); }
        *(float4*)&C[(size_t)(row0 + ty * 8 + r) * N + c0 + tx * 4] =
            make_float4(v0, v1, v2, v3);
    }
}

// ---------------- GAT aggregate (H=4, F=256): TWO warps per node ----------------
__global__ void warp_agg4_kernel(const float* __restrict__ h, const int* __restrict__ nbr,
                                 const float* __restrict__ als, const float* __restrict__ ald,
                                 const float* __restrict__ bias, float* __restrict__ out) {
    int warp = threadIdx.x >> 5, lane = threadIdx.x & 31;
    int i = blockIdx.x * 4 + (warp >> 1);
    int half = warp & 1;

    int nbr_j = i;
    if (lane < 16) nbr_j = nbr[i * KNB + lane];

    float2 sv = *(const float2*)&als[nbr_j * 4 + half * 2];
    float2 dv = *(const float2*)&ald[i * 4 + half * 2];
    float e0 = sv.x + dv.x, e1 = sv.y + dv.y;
    e0 = e0 > 0.f ? e0 : 0.2f * e0;
    e1 = e1 > 0.f ? e1 : 0.2f * e1;
    float m0 = lane < 17 ? e0 : -1e30f, m1 = lane < 17 ? e1 : -1e30f;
#pragma unroll
    for (int off = 16; off > 0; off >>= 1) {
        m0 = fmaxf(m0, __shfl_xor_sync(0xffffffffu, m0, off));
        m1 = fmaxf(m1, __shfl_xor_sync(0xffffffffu, m1, off));
    }
    float x0 = lane < 17 ? __expf(e0 - m0) : 0.f;
    float x1 = lane < 17 ? __expf(e1 - m1) : 0.f;
    float d0 = x0, d1 = x1;
#pragma unroll
    for (int off = 16; off > 0; off >>= 1) {
        d0 += __shfl_xor_sync(0xffffffffu, d0, off);
        d1 += __shfl_xor_sync(0xffffffffu, d1, off);
    }
    float al0 = x0 / d0;
    float al1 = x1 / d1;

    float al1_up = __shfl_up_sync(0xffffffffu, al1, 16);
    float alpha_sel = (lane < 16) ? al0 : al1_up;

    int fbase = half * 128 + lane * 4;
    float4 acc = make_float4(0.f, 0.f, 0.f, 0.f);
#pragma unroll
    for (int j = 0; j < 16; j++) {
        int g = __shfl_sync(0xffffffffu, nbr_j, j);
        float a = __shfl_sync(0xffffffffu, alpha_sel, j, 16);
        float4 v = *(const float4*)(h + g * 256 + fbase);
        acc.x += a * v.x; acc.y += a * v.y; acc.z += a * v.z; acc.w += a * v.w;
    }
    {
        float a0s = __shfl_sync(0xffffffffu, al0, 16);
        float a1s = __shfl_sync(0xffffffffu, al1, 16);
        float a = (lane < 16) ? a0s : a1s;
        float4 v = *(const float4*)(h + i * 256 + fbase);
        acc.x += a * v.x; acc.y += a * v.y; acc.z += a * v.z; acc.w += a * v.w;
    }
    float4 bb = *(const float4*)&bias[fbase];
    float4 o = make_float4(geluf(acc.x + bb.x), geluf(acc.y + bb.y),
                           geluf(acc.z + bb.z), geluf(acc.w + bb.w));
    *(float4*)&out[i * 256 + fbase] = o;
}

// ---------------- GAT aggregate (H=1, F=128) + residual: TWO warps per node ------
__global__ void warp_agg1_kernel(const float* __restrict__ h, const int* __restrict__ nbr,
                                 const float* __restrict__ als, const float* __restrict__ ald,
                                 const float* __restrict__ bias, float* __restrict__ out,
                                 const float* __restrict__ x6, const float* __restrict__ resW,
                                 const float* __restrict__ resb) {
    int warp = threadIdx.x >> 5, lane = threadIdx.x & 31;
    int i = blockIdx.x * 4 + (warp >> 1);
    int half = warp & 1;

    int nbr_j = i;
    if (lane < 16) nbr_j = nbr[i * KNB + lane];

    float e = als[nbr_j] + ald[i];
    e = e > 0.f ? e : 0.2f * e;
    float m = lane < 17 ? e : -1e30f;
#pragma unroll
    for (int off = 16; off > 0; off >>= 1)
        m = fmaxf(m, __shfl_xor_sync(0xffffffffu, m, off));
    float xe = lane < 17 ? __expf(e - m) : 0.f;
    float den = xe;
#pragma unroll
    for (int off = 16; off > 0; off >>= 1)
        den += __shfl_xor_sync(0xffffffffu, den, off);
    float alpha = xe / den;

    int fbase = half * 64 + lane * 2;
    float2 acc = make_float2(0.f, 0.f);
#pragma unroll
    for (int j = 0; j < 17; j++) {
        int g = __shfl_sync(0xffffffffu, nbr_j, j);
        float a = __shfl_sync(0xffffffffu, alpha, j);
        float2 v = *(const float2*)(h + g * 128 + fbase);
        acc.x += a * v.x; acc.y += a * v.y;
    }
    float2 bb = *(const float2*)&bias[fbase];
    float2 o = make_float2(geluf(acc.x + bb.x), geluf(acc.y + bb.y));
    float2 r = *(const float2*)&resb[fbase];
#pragma unroll
    for (int d = 0; d < 6; d++) {
        float xv = x6[i * 6 + d];
        float2 w = *(const float2*)&resW[d * 128 + fbase];
        r.x += xv * w.x; r.y += xv * w.y;
    }
    o.x += r.x; o.y += r.y;
    *(float2*)&out[i * 128 + fbase] = o;
}

// ---------------- final ----------------
__global__ void final_kernel(const float* __restrict__ A, const float* __restrict__ W,
                             const float* __restrict__ b, float* __restrict__ out) {
    __shared__ float Ws[64 * 6];
    __shared__ float sb[6];
    int t = threadIdx.x;
    for (int k = t; k < 64 * 6; k += blockDim.x) Ws[k] = W[k];
    if (t < 6) sb[t] = b[t];
    __syncthreads();

    int i = blockIdx.x * blockDim.x + t;
    if (i >= NN) return;
    float acc[6];
#pragma unroll
    for (int o = 0; o < 6; o++) acc[o] = sb[o];
    const float4* Ar = (const float4*)(A + (size_t)i * 64);
#pragma unroll
    for (int k4 = 0; k4 < 16; k4++) {
        float4 v = Ar[k4];
        int k = k4 * 4;
#pragma unroll
        for (int o = 0; o < 6; o++) {
            acc[o] += v.x * Ws[(k + 0) * 6 + o];
            acc[o] += v.y * Ws[(k + 1) * 6 + o];
            acc[o] += v.z * Ws[(k + 2) * 6 + o];
            acc[o] += v.w * Ws[(k + 3) * 6 + o];
        }
    }
#pragma unroll
    for (int o = 0; o < 6; o++) out[(size_t)i * 6 + o] = acc[o];
}

// ---------------- launch ----------------
extern "C" void kernel_launch(void* const* d_in, const int* in_sizes, int n_in,
                              void* d_out, int out_size) {
    const float* x    = (const float*)d_in[0];
    const float* W1   = (const float*)d_in[1];
    const float* as1  = (const float*)d_in[2];
    const float* ad1  = (const float*)d_in[3];
    const float* b1   = (const float*)d_in[4];
    const float* W2   = (const float*)d_in[5];
    const float* as2  = (const float*)d_in[6];
    const float* ad2  = (const float*)d_in[7];
    const float* b2   = (const float*)d_in[8];
    const float* W3   = (const float*)d_in[9];
    const float* as3  = (const float*)d_in[10];
    const float* ad3  = (const float*)d_in[11];
    const float* b3   = (const float*)d_in[12];
    const float* resW = (const float*)d_in[13];
    const float* resb = (const float*)d_in[14];
    const float* m1W  = (const float*)d_in[15];
    const float* m1b  = (const float*)d_in[16];
    const float* m2W  = (const float*)d_in[17];
    const float* m2b  = (const float*)d_in[18];
    const float* m3W  = (const float*)d_in[19];
    const float* m3b  = (const float*)d_in[20];

    float *xp, *h, *a0, *a1, *als, *ald;
    int* nbr;
    cudaGetSymbolAddress((void**)&xp,  g_xp);
    cudaGetSymbolAddress((void**)&nbr, g_nbr);
    cudaGetSymbolAddress((void**)&h,   g_h);
    cudaGetSymbolAddress((void**)&a0,  g_act0);
    cudaGetSymbolAddress((void**)&a1,  g_act1);
    cudaGetSymbolAddress((void**)&als, g_als);
    cudaGetSymbolAddress((void**)&ald, g_ald);

    prep_kernel<<<NN / 256, 256>>>(x, xp);
    knn_kernel<<<NN / 16, 256>>>(xp, nbr);      // 2 queries per warp, 4-chunk batch

    // GAT layer 1 (6 -> 256, H=4)
    gemm6_kernel<<<NN / 8, 256>>>(x, W1, as1, ad1, h, als, ald);
    warp_agg4_kernel<<<NN / 4, 256>>>(h, nbr, als, ald, b1, a0);

    // GAT layer 2 (256 -> 256, H=4): tf32 MMA + fused logits
    gemm_mma_kernel<<<dim3(NN / 128, 2), 256>>>(a0, W2, nullptr, h, 256, 256, 0,
                                                as2, ad2, als, ald, 4);
    warp_agg4_kernel<<<NN / 4, 256>>>(h, nbr, als, ald, b2, a1);

    // GAT layer 3 (256 -> 128, H=1) + fused residual
    gemm_mma_kernel<<<dim3(NN / 128, 1), 256>>>(a1, W3, nullptr, h, 256, 128, 0,
                                                as3, ad3, als, ald, 1);
    warp_agg1_kernel<<<NN / 4, 256>>>(h, nbr, als, ald, b3, a0, x, resW, resb);

    // MLP
    gemm_mma_kernel<<<dim3(NN / 128, 1), 256>>>(a0, m1W, m1b, a1, 128, 128, 1,
                                                nullptr, nullptr, nullptr, nullptr, 0);
    gemm_tile_kernel<<<dim3(NN / 128, 1), 256>>>(a1, m2W, m2b, h, 128, 64, 1);
    final_kernel<<<NN / 128, 128>>>(h, m3W, m3b, (float*)d_out);
}

// round 16
// speedup vs baseline: 1.3309x; 1.0157x over previous
#include <cuda_runtime.h>
#include <cuda_fp16.h>
#include <math.h>

#define NN 16384      // total nodes (B*N)
#define NB 4096       // nodes per batch
#define KNB 16        // kNN K

// ---------------- scratch ----------------
__device__ float  g_xp[NN * 8];
__device__ int    g_nbr[NN * KNB];
__device__ __half g_h[NN * 256];          // fp16 gather array (also fp32 scratch for t2)
__device__ float  g_act0[NN * 256];
__device__ float  g_act1[NN * 256];
__device__ float  g_als[NN * 4];
__device__ float  g_ald[NN * 4];

__device__ __forceinline__ float geluf(float v) {
    return 0.5f * v * (1.0f + erff(v * 0.7071067811865476f));
}

__device__ __forceinline__ float cvt_tf32(float x) {
    unsigned r;
    asm("cvt.rna.tf32.f32 %0, %1;" : "=r"(r) : "f"(x));
    return __uint_as_float(r);
}

__device__ __forceinline__ void mma8(float* d, const unsigned* a, const unsigned* b) {
    asm volatile(
        "mma.sync.aligned.m16n8k8.row.col.f32.tf32.tf32.f32 "
        "{%0,%1,%2,%3}, {%4,%5,%6,%7}, {%8,%9}, {%0,%1,%2,%3};"
        : "+f"(d[0]), "+f"(d[1]), "+f"(d[2]), "+f"(d[3])
        : "r"(a[0]), "r"(a[1]), "r"(a[2]), "r"(a[3]), "r"(b[0]), "r"(b[1]));
}

__device__ __forceinline__ unsigned smem_u32(const void* p) {
    return (unsigned)__cvta_generic_to_shared(p);
}

__device__ __forceinline__ void ldsm_x4(unsigned* r, unsigned addr) {
    asm volatile("ldmatrix.sync.aligned.m8n8.x4.shared.b16 {%0,%1,%2,%3}, [%4];"
        : "=r"(r[0]), "=r"(r[1]), "=r"(r[2]), "=r"(r[3]) : "r"(addr));
}

// ---------------- kNN: warp handles TWO queries; 4-chunk batched loads ----------
__global__ void __launch_bounds__(256) knn_kernel(const float* __restrict__ xp,
                                                  int* __restrict__ nbr) {
    int gwarp = (blockIdx.x * blockDim.x + threadIdx.x) >> 5;
    int lane = threadIdx.x & 31;
    int q0 = gwarp * 2, q1 = q0 + 1;
    int base = q0 & ~(NB - 1);

    const float4* xp4 = (const float4*)xp;
    float4 qa0 = xp4[(size_t)q0 * 2], qa1 = xp4[(size_t)q0 * 2 + 1];
    float4 qb0 = xp4[(size_t)q1 * 2], qb1 = xp4[(size_t)q1 * 2 + 1];
    float sqa = qa1.z, sqb = qb1.z;

    float s_d = 1e30f;
    int   s_i = -1;
    int ll = lane & 15;

    for (int j0 = 0; j0 < NB; j0 += 128) {
        float da[4], db[4];
#pragma unroll
        for (int c = 0; c < 4; c++) {
            int g = base + j0 + c * 32 + lane;
            float4 c0 = xp4[(size_t)g * 2];
            float4 c1 = xp4[(size_t)g * 2 + 1];
            float dA = sqa + c1.z - 2.0f * (qa0.x * c0.x + qa0.y * c0.y + qa0.z * c0.z
                     + qa0.w * c0.w + qa1.x * c1.x + qa1.y * c1.y);
            float dB = sqb + c1.z - 2.0f * (qb0.x * c0.x + qb0.y * c0.y + qb0.z * c0.z
                     + qb0.w * c0.w + qb1.x * c1.x + qb1.y * c1.y);
            if (g == q0) dA = 1e30f;
            if (g == q1) dB = 1e30f;
            da[c] = dA; db[c] = dB;
        }
#pragma unroll
        for (int c = 0; c < 4; c++) {
            float ta = __shfl_sync(0xffffffffu, s_d, 15);
            float tb = __shfl_sync(0xffffffffu, s_d, 31);
            unsigned ba = __ballot_sync(0xffffffffu, da[c] < ta);
            unsigned bb = __ballot_sync(0xffffffffu, db[c] < tb);
            unsigned ball = ba | bb;
            while (ball) {
                int src = __ffs(ball) - 1;
                ball &= ball - 1;
                float va = __shfl_sync(0xffffffffu, da[c], src);
                float vb = __shfl_sync(0xffffffffu, db[c], src);
                float v = (lane < 16) ? va : vb;
                bool act = (lane < 16) ? ((ba >> src) & 1u) : ((bb >> src) & 1u);
                float up_d = __shfl_up_sync(0xffffffffu, s_d, 1, 16);
                int   up_i = __shfl_up_sync(0xffffffffu, s_i, 1, 16);
                unsigned lt = __ballot_sync(0xffffffffu, s_d < v);
                int pos = (lane < 16) ? __popc(lt & 0xFFFFu) : __popc(lt >> 16);
                if (act && pos < 16) {
                    if (ll == pos)      { s_d = v;    s_i = base + j0 + c * 32 + src; }
                    else if (ll > pos)  { s_d = up_d; s_i = up_i; }
                }
            }
        }
    }
    if (lane < 16) nbr[q0 * KNB + ll] = s_i;
    else           nbr[q1 * KNB + ll] = s_i;
}

// ---------------- layer-1 GEMM (K=6) + direct logits + fused prep --------------
__global__ void gemm6_kernel(const float* __restrict__ x, const float* __restrict__ W,
                             const float* __restrict__ a_s, const float* __restrict__ a_d,
                             __half* __restrict__ h, float* __restrict__ als,
                             float* __restrict__ ald, float* __restrict__ xp) {
    __shared__ float sW[6 * 256];
    __shared__ float sAs[256], sAd[256];
    int t = threadIdx.x;
    for (int i = t; i < 6 * 256; i += 256) sW[i] = W[i];
    sAs[t] = a_s[t]; sAd[t] = a_d[t];
    __syncthreads();

    int warp = t >> 5, lane = t & 31;
    int node = blockIdx.x * 8 + warp;
    float xr[6];
    float nrm = 0.f;
#pragma unroll
    for (int d = 0; d < 6; d++) { xr[d] = x[node * 6 + d]; nrm += xr[d] * xr[d]; }
    if (lane == 0) {    // fused prep: padded xp row
        *(float4*)&xp[node * 8]     = make_float4(xr[0], xr[1], xr[2], xr[3]);
        *(float4*)&xp[node * 8 + 4] = make_float4(xr[4], xr[5], nrm, 0.f);
    }

    int cbase = lane * 8;
    float out[8];
#pragma unroll
    for (int c = 0; c < 8; c++) {
        float s = 0.f;
#pragma unroll
        for (int d = 0; d < 6; d++) s += xr[d] * sW[d * 256 + cbase + c];
        out[c] = s;
    }
    union { __half2 h2[4]; uint4 u; } pk;
#pragma unroll
    for (int c = 0; c < 4; c++) pk.h2[c] = __floats2half2_rn(out[2 * c], out[2 * c + 1]);
    *(uint4*)&h[(size_t)node * 256 + cbase] = pk.u;

    float ps = 0.f, pd = 0.f;
#pragma unroll
    for (int c = 0; c < 8; c++) {
        ps += out[c] * sAs[cbase + c];
        pd += out[c] * sAd[cbase + c];
    }
#pragma unroll
    for (int off = 1; off <= 4; off <<= 1) {
        ps += __shfl_xor_sync(0xffffffffu, ps, off);
        pd += __shfl_xor_sync(0xffffffffu, pd, off);
    }
    if ((lane & 7) == 0) {
        int hh = lane >> 3;
        als[node * 4 + hh] = ps;
        ald[node * 4 + hh] = pd;
    }
}

// ---------------- tf32 tensor-core GEMM: 128x128 tile, ldmatrix A frags ---------
// outHalf: store C as __half (for gather array h); else fp32.
__global__ void __launch_bounds__(256) gemm_mma_kernel(
        const float* __restrict__ A, const float* __restrict__ W,
        const float* __restrict__ bias, void* __restrict__ Cv,
        int K, int N, int actGelu, int outHalf,
        const float* __restrict__ a_s, const float* __restrict__ a_d,
        float* __restrict__ als, float* __restrict__ ald, int H) {
    __shared__ __align__(16) float As[128][36];
    __shared__ __align__(16) float Ws[32][136];
    __shared__ float s_ls[256], s_ld[256];

    int t = threadIdx.x;
    int warp = t >> 5, lane = t & 31;
    int gid = lane >> 2, tig = lane & 3;
    int wm0 = (warp >> 2) * 64;
    int wn0 = (warp & 3) * 32;
    int row0 = blockIdx.x * 128;
    int c0 = blockIdx.y * 128;

    if (als) { s_ls[t] = 0.f; s_ld[t] = 0.f; }

    float acc[4][4][4];
#pragma unroll
    for (int mt = 0; mt < 4; mt++)
#pragma unroll
        for (int nt = 0; nt < 4; nt++)
#pragma unroll
            for (int r = 0; r < 4; r++) acc[mt][nt][r] = 0.f;

    int aR = t >> 3, aKq = (t & 7) * 4;
    int wK = t >> 5, wC = (t & 31) * 4;

    int row_sel = (lane & 7) + ((lane >> 3) & 1) * 8;
    int ksel = (lane >> 4) & 1;
    unsigned aAddrBase = smem_u32(&As[0][0]) + (unsigned)((wm0 + row_sel) * 144 + ksel * 16);

    float4 aPf[4], wPf[4];
#pragma unroll
    for (int i = 0; i < 4; i++)
        aPf[i] = *(const float4*)&A[(size_t)(row0 + aR + i * 32) * K + aKq];
#pragma unroll
    for (int i = 0; i < 4; i++)
        wPf[i] = *(const float4*)&W[(size_t)(wK + i * 8) * N + c0 + wC];

    int nch = K >> 5;
    for (int ch = 0; ch < nch; ch++) {
#pragma unroll
        for (int i = 0; i < 4; i++) {
            As[aR + i * 32][aKq + 0] = cvt_tf32(aPf[i].x);
            As[aR + i * 32][aKq + 1] = cvt_tf32(aPf[i].y);
            As[aR + i * 32][aKq + 2] = cvt_tf32(aPf[i].z);
            As[aR + i * 32][aKq + 3] = cvt_tf32(aPf[i].w);
        }
#pragma unroll
        for (int i = 0; i < 4; i++) {
            Ws[wK + i * 8][wC + 0] = cvt_tf32(wPf[i].x);
            Ws[wK + i * 8][wC + 1] = cvt_tf32(wPf[i].y);
            Ws[wK + i * 8][wC + 2] = cvt_tf32(wPf[i].z);
            Ws[wK + i * 8][wC + 3] = cvt_tf32(wPf[i].w);
        }
        __syncthreads();

        if (ch + 1 < nch) {
            int k0 = (ch + 1) << 5;
#pragma unroll
            for (int i = 0; i < 4; i++)
                aPf[i] = *(const float4*)&A[(size_t)(row0 + aR + i * 32) * K + k0 + aKq];
#pragma unroll
            for (int i = 0; i < 4; i++)
                wPf[i] = *(const float4*)&W[(size_t)(k0 + wK + i * 8) * N + c0 + wC];
        }

#pragma unroll
        for (int kk8 = 0; kk8 < 4; kk8++) {
            int kb = kk8 * 8;
            unsigned ua[4][4], ub[4][2];
#pragma unroll
            for (int mt = 0; mt < 4; mt++)
                ldsm_x4(ua[mt], aAddrBase + (unsigned)(mt * 2304 + kk8 * 32));
#pragma unroll
            for (int nt = 0; nt < 4; nt++) {
                int cn = wn0 + nt * 8 + gid;
                ub[nt][0] = __float_as_uint(Ws[kb + tig][cn]);
                ub[nt][1] = __float_as_uint(Ws[kb + tig + 4][cn]);
            }
#pragma unroll
            for (int mt = 0; mt < 4; mt++)
#pragma unroll
                for (int nt = 0; nt < 4; nt++)
                    mma8(acc[mt][nt], ua[mt], ub[nt]);
        }
        __syncthreads();
    }

    if (als) {
        float asv[4][2], adv[4][2];
#pragma unroll
        for (int nt = 0; nt < 4; nt++) {
            int col = c0 + wn0 + nt * 8 + 2 * tig;
            asv[nt][0] = a_s[col]; asv[nt][1] = a_s[col + 1];
            adv[nt][0] = a_d[col]; adv[nt][1] = a_d[col + 1];
        }
        int lh = (H == 4) ? (wn0 >> 6) : 0;
#pragma unroll
        for (int mt = 0; mt < 4; mt++) {
            float p0s = 0.f, p1s = 0.f, p0d = 0.f, p1d = 0.f;
#pragma unroll
            for (int nt = 0; nt < 4; nt++) {
                p0s += acc[mt][nt][0] * asv[nt][0] + acc[mt][nt][1] * asv[nt][1];
                p1s += acc[mt][nt][2] * asv[nt][0] + acc[mt][nt][3] * asv[nt][1];
                p0d += acc[mt][nt][0] * adv[nt][0] + acc[mt][nt][1] * adv[nt][1];
                p1d += acc[mt][nt][2] * adv[nt][0] + acc[mt][nt][3] * adv[nt][1];
            }
#pragma unroll
            for (int off = 1; off <= 2; off <<= 1) {
                p0s += __shfl_xor_sync(0xffffffffu, p0s, off);
                p1s += __shfl_xor_sync(0xffffffffu, p1s, off);
                p0d += __shfl_xor_sync(0xffffffffu, p0d, off);
                p1d += __shfl_xor_sync(0xffffffffu, p1d, off);
            }
            if (tig == 0) {
                int rl = wm0 + mt * 16 + gid;
                atomicAdd(&s_ls[lh * 128 + rl], p0s);
                atomicAdd(&s_ls[lh * 128 + rl + 8], p1s);
                atomicAdd(&s_ld[lh * 128 + rl], p0d);
                atomicAdd(&s_ld[lh * 128 + rl + 8], p1d);
            }
        }
        __syncthreads();
        if (H == 4) {
            int row = t & 127, hh = (c0 >> 6) + (t >> 7);
            als[(size_t)(row0 + row) * 4 + hh] = s_ls[(t >> 7) * 128 + row];
            ald[(size_t)(row0 + row) * 4 + hh] = s_ld[(t >> 7) * 128 + row];
        } else if (t < 128) {
            als[row0 + t] = s_ls[t];
            ald[row0 + t] = s_ld[t];
        }
    }

    float bb[4][2];
#pragma unroll
    for (int nt = 0; nt < 4; nt++) {
        if (bias) {
            int col = c0 + wn0 + nt * 8 + 2 * tig;
            bb[nt][0] = bias[col]; bb[nt][1] = bias[col + 1];
        } else { bb[nt][0] = 0.f; bb[nt][1] = 0.f; }
    }
#pragma unroll
    for (int mt = 0; mt < 4; mt++) {
#pragma unroll
        for (int rs = 0; rs < 2; rs++) {
            int row = row0 + wm0 + mt * 16 + gid + rs * 8;
#pragma unroll
            for (int nt = 0; nt < 4; nt++) {
                float v0 = acc[mt][nt][2 * rs] + bb[nt][0];
                float v1 = acc[mt][nt][2 * rs + 1] + bb[nt][1];
                if (actGelu) { v0 = geluf(v0); v1 = geluf(v1); }
                size_t idx = (size_t)row * N + c0 + wn0 + nt * 8 + 2 * tig;
                if (outHalf)
                    *(__half2*)&((__half*)Cv)[idx] = __floats2half2_rn(v0, v1);
                else
                    *(float2*)&((float*)Cv)[idx] = make_float2(v0, v1);
            }
        }
    }
}

// ---------------- 128x64 FFMA GEMM (MLP layer 2, N=64) ----------------
__global__ void gemm_tile_kernel(const float* __restrict__ A, const float* __restrict__ W,
                                 const float* __restrict__ bias, float* __restrict__ C,
                                 int K, int N, int actGelu) {
    __shared__ float As[16][136];
    __shared__ float Ws[16][64];

    int t = threadIdx.x;
    int tx = t & 15;
    int ty = t >> 4;
    int row0 = blockIdx.x * 128;
    int c0 = blockIdx.y * 64;

    float acc[8][4];
#pragma unroll
    for (int r = 0; r < 8; r++)
#pragma unroll
        for (int c = 0; c < 4; c++) acc[r][c] = 0.f;

    float4 aReg[2], wReg;
    int aR[2], aKq[2];
#pragma unroll
    for (int i = 0; i < 2; i++) {
        int lin = t + i * 256;
        aR[i] = lin >> 2;
        aKq[i] = lin & 3;
    }
    int wK = t >> 4, wC = (t & 15) * 4;

#pragma unroll
    for (int i = 0; i < 2; i++)
        aReg[i] = *(const float4*)&A[(size_t)(row0 + aR[i]) * K + aKq[i] * 4];
    wReg = *(const float4*)&W[(size_t)wK * N + c0 + wC];

    int nchunks = K >> 4;
    for (int ch = 0; ch < nchunks; ch++) {
#pragma unroll
        for (int i = 0; i < 2; i++) {
            As[aKq[i] * 4 + 0][aR[i]] = aReg[i].x;
            As[aKq[i] * 4 + 1][aR[i]] = aReg[i].y;
            As[aKq[i] * 4 + 2][aR[i]] = aReg[i].z;
            As[aKq[i] * 4 + 3][aR[i]] = aReg[i].w;
        }
        *(float4*)&Ws[wK][wC] = wReg;
        __syncthreads();

        if (ch + 1 < nchunks) {
            int k0 = (ch + 1) << 4;
#pragma unroll
            for (int i = 0; i < 2; i++)
                aReg[i] = *(const float4*)&A[(size_t)(row0 + aR[i]) * K + k0 + aKq[i] * 4];
            wReg = *(const float4*)&W[(size_t)(k0 + wK) * N + c0 + wC];
        }

#pragma unroll
        for (int k = 0; k < 16; k++) {
            float4 a0 = *(const float4*)&As[k][ty * 8];
            float4 a1 = *(const float4*)&As[k][ty * 8 + 4];
            float4 wv = *(const float4*)&Ws[k][tx * 4];
            acc[0][0] += a0.x * wv.x; acc[0][1] += a0.x * wv.y; acc[0][2] += a0.x * wv.z; acc[0][3] += a0.x * wv.w;
            acc[1][0] += a0.y * wv.x; acc[1][1] += a0.y * wv.y; acc[1][2] += a0.y * wv.z; acc[1][3] += a0.y * wv.w;
            acc[2][0] += a0.z * wv.x; acc[2][1] += a0.z * wv.y; acc[2][2] += a0.z * wv.z; acc[2][3] += a0.z * wv.w;
            acc[3][0] += a0.w * wv.x; acc[3][1] += a0.w * wv.y; acc[3][2] += a0.w * wv.z; acc[3][3] += a0.w * wv.w;
            acc[4][0] += a1.x * wv.x; acc[4][1] += a1.x * wv.y; acc[4][2] += a1.x * wv.z; acc[4][3] += a1.x * wv.w;
            acc[5][0] += a1.y * wv.x; acc[5][1] += a1.y * wv.y; acc[5][2] += a1.y * wv.z; acc[5][3] += a1.y * wv.w;
            acc[6][0] += a1.z * wv.x; acc[6][1] += a1.z * wv.y; acc[6][2] += a1.z * wv.z; acc[6][3] += a1.z * wv.w;
            acc[7][0] += a1.w * wv.x; acc[7][1] += a1.w * wv.y; acc[7][2] += a1.w * wv.z; acc[7][3] += a1.w * wv.w;
        }
        __syncthreads();
    }

    float4 bb = make_float4(0.f, 0.f, 0.f, 0.f);
    if (bias) bb = *(const float4*)&bias[c0 + tx * 4];
#pragma unroll
    for (int r = 0; r < 8; r++) {
        float v0 = acc[r][0] + bb.x, v1 = acc[r][1] + bb.y,
              v2 = acc[r][2] + bb.z, v3 = acc[r][3] + bb.w;
        if (actGelu) { v0 = geluf(v0); v1 = geluf(v1); v2 = geluf(v2); v3 = geluf(v3); }
        *(float4*)&C[(size_t)(row0 + ty * 8 + r) * N + c0 + tx * 4] =
            make_float4(v0, v1, v2, v3);
    }
}

// ---------------- GAT aggregate (H=4, F=256): TWO warps per node, fp16 h --------
__global__ void warp_agg4_kernel(const __half* __restrict__ h, const int* __restrict__ nbr,
                                 const float* __restrict__ als, const float* __restrict__ ald,
                                 const float* __restrict__ bias, float* __restrict__ out) {
    int warp = threadIdx.x >> 5, lane = threadIdx.x & 31;
    int i = blockIdx.x * 4 + (warp >> 1);
    int half = warp & 1;

    int nbr_j = i;
    if (lane < 16) nbr_j = nbr[i * KNB + lane];

    float2 sv = *(const float2*)&als[nbr_j * 4 + half * 2];
    float2 dv = *(const float2*)&ald[i * 4 + half * 2];
    float e0 = sv.x + dv.x, e1 = sv.y + dv.y;
    e0 = e0 > 0.f ? e0 : 0.2f * e0;
    e1 = e1 > 0.f ? e1 : 0.2f * e1;
    float m0 = lane < 17 ? e0 : -1e30f, m1 = lane < 17 ? e1 : -1e30f;
#pragma unroll
    for (int off = 16; off > 0; off >>= 1) {
        m0 = fmaxf(m0, __shfl_xor_sync(0xffffffffu, m0, off));
        m1 = fmaxf(m1, __shfl_xor_sync(0xffffffffu, m1, off));
    }
    float x0 = lane < 17 ? __expf(e0 - m0) : 0.f;
    float x1 = lane < 17 ? __expf(e1 - m1) : 0.f;
    float d0 = x0, d1 = x1;
#pragma unroll
    for (int off = 16; off > 0; off >>= 1) {
        d0 += __shfl_xor_sync(0xffffffffu, d0, off);
        d1 += __shfl_xor_sync(0xffffffffu, d1, off);
    }
    float al0 = x0 / d0;
    float al1 = x1 / d1;

    float al1_up = __shfl_up_sync(0xffffffffu, al1, 16);
    float alpha_sel = (lane < 16) ? al0 : al1_up;

    int fbase = half * 128 + lane * 4;
    float4 acc = make_float4(0.f, 0.f, 0.f, 0.f);
#pragma unroll
    for (int j = 0; j < 16; j++) {
        int g = __shfl_sync(0xffffffffu, nbr_j, j);
        float a = __shfl_sync(0xffffffffu, alpha_sel, j, 16);
        uint2 raw = *(const uint2*)(h + (size_t)g * 256 + fbase);
        float2 f0 = __half22float2(*(__half2*)&raw.x);
        float2 f1 = __half22float2(*(__half2*)&raw.y);
        acc.x += a * f0.x; acc.y += a * f0.y; acc.z += a * f1.x; acc.w += a * f1.y;
    }
    {
        float a0s = __shfl_sync(0xffffffffu, al0, 16);
        float a1s = __shfl_sync(0xffffffffu, al1, 16);
        float a = (lane < 16) ? a0s : a1s;
        uint2 raw = *(const uint2*)(h + (size_t)i * 256 + fbase);
        float2 f0 = __half22float2(*(__half2*)&raw.x);
        float2 f1 = __half22float2(*(__half2*)&raw.y);
        acc.x += a * f0.x; acc.y += a * f0.y; acc.z += a * f1.x; acc.w += a * f1.y;
    }
    float4 bb = *(const float4*)&bias[fbase];
    float4 o = make_float4(geluf(acc.x + bb.x), geluf(acc.y + bb.y),
                           geluf(acc.z + bb.z), geluf(acc.w + bb.w));
    *(float4*)&out[(size_t)i * 256 + fbase] = o;
}

// ---------------- GAT aggregate (H=1, F=128) + residual, fp16 h -----------------
__global__ void warp_agg1_kernel(const __half* __restrict__ h, const int* __restrict__ nbr,
                                 const float* __restrict__ als, const float* __restrict__ ald,
                                 const float* __restrict__ bias, float* __restrict__ out,
                                 const float* __restrict__ x6, const float* __restrict__ resW,
                                 const float* __restrict__ resb) {
    int warp = threadIdx.x >> 5, lane = threadIdx.x & 31;
    int i = blockIdx.x * 4 + (warp >> 1);
    int half = warp & 1;

    int nbr_j = i;
    if (lane < 16) nbr_j = nbr[i * KNB + lane];

    float e = als[nbr_j] + ald[i];
    e = e > 0.f ? e : 0.2f * e;
    float m = lane < 17 ? e : -1e30f;
#pragma unroll
    for (int off = 16; off > 0; off >>= 1)
        m = fmaxf(m, __shfl_xor_sync(0xffffffffu, m, off));
    float xe = lane < 17 ? __expf(e - m) : 0.f;
    float den = xe;
#pragma unroll
    for (int off = 16; off > 0; off >>= 1)
        den += __shfl_xor_sync(0xffffffffu, den, off);
    float alpha = xe / den;

    int fbase = half * 64 + lane * 2;
    float2 acc = make_float2(0.f, 0.f);
#pragma unroll
    for (int j = 0; j < 17; j++) {
        int g = __shfl_sync(0xffffffffu, nbr_j, j);
        float a = __shfl_sync(0xffffffffu, alpha, j);
        float2 f = __half22float2(*(const __half2*)(h + (size_t)g * 128 + fbase));
        acc.x += a * f.x; acc.y += a * f.y;
    }
    float2 bb = *(const float2*)&bias[fbase];
    float2 o = make_float2(geluf(acc.x + bb.x), geluf(acc.y + bb.y));
    float2 r = *(const float2*)&resb[fbase];
#pragma unroll
    for (int d = 0; d < 6; d++) {
        float xv = x6[i * 6 + d];
        float2 w = *(const float2*)&resW[d * 128 + fbase];
        r.x += xv * w.x; r.y += xv * w.y;
    }
    o.x += r.x; o.y += r.y;
    *(float2*)&out[(size_t)i * 128 + fbase] = o;
}

// ---------------- final ----------------
__global__ void final_kernel(const float* __restrict__ A, const float* __restrict__ W,
                             const float* __restrict__ b, float* __restrict__ out) {
    __shared__ float Ws[64 * 6];
    __shared__ float sb[6];
    int t = threadIdx.x;
    for (int k = t; k < 64 * 6; k += blockDim.x) Ws[k] = W[k];
    if (t < 6) sb[t] = b[t];
    __syncthreads();

    int i = blockIdx.x * blockDim.x + t;
    if (i >= NN) return;
    float acc[6];
#pragma unroll
    for (int o = 0; o < 6; o++) acc[o] = sb[o];
    const float4* Ar = (const float4*)(A + (size_t)i * 64);
#pragma unroll
    for (int k4 = 0; k4 < 16; k4++) {
        float4 v = Ar[k4];
        int k = k4 * 4;
#pragma unroll
        for (int o = 0; o < 6; o++) {
            acc[o] += v.x * Ws[(k + 0) * 6 + o];
            acc[o] += v.y * Ws[(k + 1) * 6 + o];
            acc[o] += v.z * Ws[(k + 2) * 6 + o];
            acc[o] += v.w * Ws[(k + 3) * 6 + o];
        }
    }
#pragma unroll
    for (int o = 0; o < 6; o++) out[(size_t)i * 6 + o] = acc[o];
}

// ---------------- launch ----------------
extern "C" void kernel_launch(void* const* d_in, const int* in_sizes, int n_in,
                              void* d_out, int out_size) {
    const float* x    = (const float*)d_in[0];
    const float* W1   = (const float*)d_in[1];
    const float* as1  = (const float*)d_in[2];
    const float* ad1  = (const float*)d_in[3];
    const float* b1   = (const float*)d_in[4];
    const float* W2   = (const float*)d_in[5];
    const float* as2  = (const float*)d_in[6];
    const float* ad2  = (const float*)d_in[7];
    const float* b2   = (const float*)d_in[8];
    const float* W3   = (const float*)d_in[9];
    const float* as3  = (const float*)d_in[10];
    const float* ad3  = (const float*)d_in[11];
    const float* b3   = (const float*)d_in[12];
    const float* resW = (const float*)d_in[13];
    const float* resb = (const float*)d_in[14];
    const float* m1W  = (const float*)d_in[15];
    const float* m1b  = (const float*)d_in[16];
    const float* m2W  = (const float*)d_in[17];
    const float* m2b  = (const float*)d_in[18];
    const float* m3W  = (const float*)d_in[19];
    const float* m3b  = (const float*)d_in[20];

    float *xp, *a0, *a1, *als, *ald;
    __half* h;
    int* nbr;
    cudaGetSymbolAddress((void**)&xp,  g_xp);
    cudaGetSymbolAddress((void**)&nbr, g_nbr);
    cudaGetSymbolAddress((void**)&h,   g_h);
    cudaGetSymbolAddress((void**)&a0,  g_act0);
    cudaGetSymbolAddress((void**)&a1,  g_act1);
    cudaGetSymbolAddress((void**)&als, g_als);
    cudaGetSymbolAddress((void**)&ald, g_ald);
    float* t2 = (float*)h;   // fp32 scratch reuse (h dead after agg1)

    // GAT layer 1 GEMM (fused prep) -> kNN -> aggregate
    gemm6_kernel<<<NN / 8, 256>>>(x, W1, as1, ad1, h, als, ald, xp);
    knn_kernel<<<NN / 16, 256>>>(xp, nbr);
    warp_agg4_kernel<<<NN / 4, 256>>>(h, nbr, als, ald, b1, a0);

    // GAT layer 2 (256 -> 256, H=4): tf32 MMA + fused logits, half h out
    gemm_mma_kernel<<<dim3(NN / 128, 2), 256>>>(a0, W2, nullptr, h, 256, 256, 0, 1,
                                                as2, ad2, als, ald, 4);
    warp_agg4_kernel<<<NN / 4, 256>>>(h, nbr, als, ald, b2, a1);

    // GAT layer 3 (256 -> 128, H=1) + fused residual
    gemm_mma_kernel<<<dim3(NN / 128, 1), 256>>>(a1, W3, nullptr, h, 256, 128, 0, 1,
                                                as3, ad3, als, ald, 1);
    warp_agg1_kernel<<<NN / 4, 256>>>(h, nbr, als, ald, b3, a0, x, resW, resb);

    // MLP
    gemm_mma_kernel<<<dim3(NN / 128, 1), 256>>>(a0, m1W, m1b, a1, 128, 128, 1, 0,
                                                nullptr, nullptr, nullptr, nullptr, 0);
    gemm_tile_kernel<<<dim3(NN / 128, 1), 256>>>(a1, m2W, m2b, t2, 128, 64, 1);
    final_kernel<<<NN / 128, 128>>>(t2, m3W, m3b, (float*)d_out);
}